// round 7
// baseline (speedup 1.0000x reference)
#include <cuda_runtime.h>
#include <cuda_fp16.h>
#include <math.h>
#include <stdint.h>

#define D_DIM 1024
#define H_DIM 2048
#define E_NUM 8
#define CAP   8192
#define N_TOK 8192
#define BM 128
#define BK 64                            // halves per slab = 128 B rows

#define A_BYTES 16384                    // 128 rows x 128B
#define NSTAGE 4

// ---------------- device scratch ----------------
__device__ int    g_cnt[E_NUM];
__device__ int    g_off[E_NUM];
__device__ int    g_tok[E_NUM * CAP];
__device__ float  g_gate[E_NUM * CAP];
__device__ int    g_inv[N_TOK * 2];
__device__ float  g_imp[E_NUM];
__device__ float  g_ent;
__device__ __half g_xh[(size_t)N_TOK * D_DIM];            // x as half, k-permuted
__device__ __half g_hh[(size_t)N_TOK * 2 * H_DIM];        // h as half, k-permuted
__device__ float  g_y[(size_t)N_TOK * 2 * D_DIM];
__device__ __half g_w1h[(size_t)E_NUM * H_DIM * D_DIM];   // [e][n=H][k'=D]
__device__ __half g_w2h[(size_t)E_NUM * D_DIM * H_DIM];   // [e][n=D][k'=H]

// k-group permutation: storage slot s holds source k = KORD[s]
__device__ __constant__ int KORD[16] = {0,1,8,9,2,3,10,11,4,5,12,13,6,7,14,15};
__device__ __forceinline__ int kslot(int r) {      // r = k & 15, even
    return (((r >> 1) & 3) << 2) + ((r >> 3) << 1);
}

// ---------------- helpers ----------------
__device__ __forceinline__ uint32_t smem_u32(const void* p) {
    uint32_t a;
    asm("{ .reg .u64 t; cvta.to.shared.u64 t, %1; cvt.u32.u64 %0, t; }" : "=r"(a) : "l"(p));
    return a;
}
#define CP16(dst, src) \
    asm volatile("cp.async.cg.shared.global [%0], [%1], 16;" :: "r"(dst), "l"(src))
#define CP_COMMIT()  asm volatile("cp.async.commit_group;" ::: "memory")
#define CP_WAIT(n)   asm volatile("cp.async.wait_group %0;" :: "n"(n) : "memory")

__device__ __forceinline__ void mma_f16(float* c, unsigned a0, unsigned a1,
                                        unsigned a2, unsigned a3,
                                        unsigned b0, unsigned b1) {
    asm volatile(
        "mma.sync.aligned.m16n8k16.row.col.f32.f16.f16.f32 "
        "{%0,%1,%2,%3}, {%4,%5,%6,%7}, {%8,%9}, {%0,%1,%2,%3};\n"
        : "+f"(c[0]), "+f"(c[1]), "+f"(c[2]), "+f"(c[3])
        : "r"(a0), "r"(a1), "r"(a2), "r"(a3), "r"(b0), "r"(b1));
}
__device__ __forceinline__ float gelu_exact(float v) {
    return 0.5f * v * (1.0f + erff(v * 0.70710678118654752440f));
}

// ---------------- small kernels ----------------
__global__ void reset_k() {
    int t = threadIdx.x;
    if (t < E_NUM) { g_cnt[t] = 0; g_imp[t] = 0.0f; }
    if (t == 0)    g_ent = 0.0f;
}

// router + x->half conversion fused (warp per token)
__global__ void router_k(const float* __restrict__ x,
                         const float* __restrict__ gW,
                         const float* __restrict__ gb) {
    int token = (blockIdx.x * blockDim.x + threadIdx.x) >> 5;
    int lane  = threadIdx.x & 31;
    if (token >= N_TOK) return;
    const float* xr = x + (size_t)token * D_DIM;
    __half* xh = g_xh + (size_t)token * D_DIM;

    float acc[8] = {0.f,0.f,0.f,0.f,0.f,0.f,0.f,0.f};
#pragma unroll
    for (int i = 0; i < 8; i++) {
        int d = lane * 4 + 128 * i;
        float4 xv = *reinterpret_cast<const float4*>(xr + d);
        int base = d & ~15, r = d & 15;
        *reinterpret_cast<__half2*>(xh + base + kslot(r)) =
            __floats2half2_rn(xv.x, xv.y);
        *reinterpret_cast<__half2*>(xh + base + kslot(r + 2)) =
            __floats2half2_rn(xv.z, xv.w);
        const float4* w = reinterpret_cast<const float4*>(gW + (size_t)d * E_NUM);
        float xs[4] = {xv.x, xv.y, xv.z, xv.w};
#pragma unroll
        for (int q = 0; q < 4; q++) {
            float4 wa = w[q * 2], wb = w[q * 2 + 1];
            acc[0] += xs[q] * wa.x; acc[1] += xs[q] * wa.y;
            acc[2] += xs[q] * wa.z; acc[3] += xs[q] * wa.w;
            acc[4] += xs[q] * wb.x; acc[5] += xs[q] * wb.y;
            acc[6] += xs[q] * wb.z; acc[7] += xs[q] * wb.w;
        }
    }
#pragma unroll
    for (int e = 0; e < 8; e++)
#pragma unroll
        for (int o = 16; o; o >>= 1) acc[e] += __shfl_xor_sync(0xffffffffu, acc[e], o);
    if (lane) return;

    float lg[8];
#pragma unroll
    for (int e = 0; e < 8; e++) lg[e] = acc[e] + gb[e];
    float mx = lg[0];
#pragma unroll
    for (int e = 1; e < 8; e++) mx = fmaxf(mx, lg[e]);
    float p[8], Z = 0.f;
#pragma unroll
    for (int e = 0; e < 8; e++) { p[e] = expf(lg[e] - mx); Z += p[e]; }
    float ent = 0.f;
#pragma unroll
    for (int e = 0; e < 8; e++) {
        p[e] /= Z;
        ent -= p[e] * logf(p[e] + 1e-8f);
        atomicAdd(&g_imp[e], p[e]);
    }
    atomicAdd(&g_ent, ent);

    int e0 = 0;
#pragma unroll
    for (int e = 1; e < 8; e++) if (lg[e] > lg[e0]) e0 = e;
    int e1 = -1;
#pragma unroll
    for (int e = 0; e < 8; e++) if (e != e0 && (e1 < 0 || lg[e] > lg[e1])) e1 = e;

    float dlt = expf(lg[e1] - lg[e0]);
    float g0 = 1.0f / (1.0f + dlt);
    float g1 = dlt / (1.0f + dlt);

    int s0 = atomicAdd(&g_cnt[e0], 1);
    g_tok[e0 * CAP + s0] = token; g_gate[e0 * CAP + s0] = g0;
    int s1 = atomicAdd(&g_cnt[e1], 1);
    g_tok[e1 * CAP + s1] = token; g_gate[e1 * CAP + s1] = g1;
    g_inv[token * 2 + 0] = e0 * CAP + s0;
    g_inv[token * 2 + 1] = e1 * CAP + s1;
}

__global__ void tail_k(float* __restrict__ out_tail) {
    if (threadIdx.x != 0 || blockIdx.x != 0) return;
    int off = 0;
    float loadv[8], impv[8];
    for (int e = 0; e < 8; e++) { g_off[e] = off; off += g_cnt[e]; }
    for (int e = 0; e < 8; e++) {
        loadv[e] = (float)g_cnt[e] / (float)N_TOK;
        impv[e]  = g_imp[e] / (float)N_TOK;
    }
    float bal = 0.f, util = 0.f;
    for (int e = 0; e < 8; e++) bal += impv[e] * loadv[e];
    bal *= (float)E_NUM;
    for (int e = 0; e < 8; e++) util -= loadv[e] * logf(loadv[e] + 1e-8f);
    out_tail[0] = bal;
    out_tail[1] = g_ent / (float)N_TOK;
    out_tail[2] = util;
    for (int e = 0; e < 8; e++) out_tail[3 + e]  = loadv[e];
    for (int e = 0; e < 8; e++) out_tail[11 + e] = impv[e];
}

// W[e][k][n] fp32 -> WT[e][n][k'] half. 64x64 tiles, full-line half writes.
__global__ void wtrans_k(const float* __restrict__ W, __half* __restrict__ WT,
                         int K, int N) {
    __shared__ float t[64][68];
    int e = blockIdx.z, n0 = blockIdx.x * 64, k0 = blockIdx.y * 64;
    const float* Ws = W + (size_t)e * K * N + (size_t)k0 * N + n0;
    __half* Wd = WT + (size_t)e * N * K;
#pragma unroll
    for (int i = 0; i < 4; i++) {
        int idx = threadIdx.x + 256 * i;     // 0..1023
        int kr = idx >> 4, c4 = idx & 15;
        float4 v = *reinterpret_cast<const float4*>(Ws + (size_t)kr * N + c4 * 4);
        *reinterpret_cast<float4*>(&t[kr][c4 * 4]) = v;
    }
    __syncthreads();
    int n = threadIdx.x >> 2, kg = (threadIdx.x & 3) * 16;
    __half hh[16];
#pragma unroll
    for (int s = 0; s < 16; s++) hh[s] = __float2half(t[kg + KORD[s]][n]);
    __half* drow = Wd + (size_t)(n0 + n) * K + k0 + kg;
    *reinterpret_cast<uint4*>(drow)     = *reinterpret_cast<uint4*>(hh);
    *reinterpret_cast<uint4*>(drow + 8) = *reinterpret_cast<uint4*>(hh + 8);
}

// ---------------- fp16 pipelined grouped GEMM ----------------
// MODE 0: BN=256, warp 64x64. A = gather(g_xh) [K=1024], B=g_w1h, gelu -> g_hh
// MODE 1: BN=128, warp 64x32. A = g_hh [K=2048], B=g_w2h, bias -> g_y
template <int MODE>
__global__ void __launch_bounds__(256, 1)
gemm_h(const float* __restrict__ bias) {
    constexpr int Kdim  = (MODE == 0) ? D_DIM : H_DIM;
    constexpr int Ncols = (MODE == 0) ? H_DIM : D_DIM;
    constexpr int BN    = (MODE == 0) ? 256 : 128;
    constexpr int NJ    = BN / 32;               // j-tiles per warp (8 or 4)
    constexpr int NBCH  = BN / 32;               // B cp.async row chunks
    constexpr int B_BYTES = BN * 128;
    constexpr int STAGE = A_BYTES + B_BYTES;
    constexpr int NS    = Kdim / BK;

    extern __shared__ char smem[];
    const int e = blockIdx.z;
    const int cnt = g_cnt[e];
    const int m_base = blockIdx.y * BM;
    if (m_base >= cnt) return;
    const int n_base = blockIdx.x * BN;
    const int hoff = g_off[e];

    const int tid = threadIdx.x, wid = tid >> 5, lane = tid & 31;
    const int g = lane >> 2, tig = lane & 3;
    const int wm = (wid & 1) * 64;
    const int wn = (wid >> 1) * (BN / 4);
    const uint32_t sb = smem_u32(smem);
    float* sBias = (float*)smem;

    if (tid < BN) sBias[tid] = bias[(size_t)e * Ncols + n_base + tid];

    // ---- cp.async assignments ----
    const int cch = tid & 7;          // 16B chunk (8 halves) within 128B row
    const int r0  = tid >> 3;         // base row 0..31
    const __half* Ab = (MODE == 0) ? (const __half*)g_xh : (const __half*)g_hh;
    const __half* Wb = (MODE == 0) ? (const __half*)g_w1h : (const __half*)g_w2h;

    const __half* aSrc[4];
#pragma unroll
    for (int i = 0; i < 4; i++) {
        int am = m_base + r0 + 32 * i;
        if (am >= cnt) am = cnt - 1;
        size_t row = (MODE == 0) ? (size_t)g_tok[e * CAP + am] : (size_t)(hoff + am);
        aSrc[i] = Ab + row * Kdim + cch * 8;
    }
    const __half* bSrc = Wb + ((size_t)e * Ncols + n_base + r0) * Kdim + cch * 8;

    const uint32_t swz = (uint32_t)((cch ^ (r0 & 7)) << 4);
    const uint32_t aDst = sb + 1024 + r0 * 128 + swz;
    const uint32_t bDst = sb + 1024 + A_BYTES + r0 * 128 + swz;

    float c[4][NJ][4];
#pragma unroll
    for (int i = 0; i < 4; i++)
#pragma unroll
        for (int j = 0; j < NJ; j++)
#pragma unroll
            for (int r = 0; r < 4; r++) c[i][j][r] = 0.f;

    auto issue = [&](int s) {
        if (s < NS) {
            const int kb = s * BK;
            const uint32_t so = (uint32_t)((s & (NSTAGE - 1)) * STAGE);
#pragma unroll
            for (int i = 0; i < 4; i++)
                CP16(aDst + so + i * 4096, aSrc[i] + kb);
#pragma unroll
            for (int i = 0; i < NBCH; i++)
                CP16(bDst + so + i * 4096, bSrc + (size_t)(32 * i) * Kdim + kb);
        }
        CP_COMMIT();
    };

    issue(0); issue(1); issue(2);

    const int aRow = (wm + g) * 128;
    const int bRow = A_BYTES + (wn + g) * 128;

    for (int s = 0; s < NS; s++) {
        CP_WAIT(2);
        __syncthreads();
        issue(s + 3);

        const char* stg = smem + 1024 + (s & (NSTAGE - 1)) * STAGE;
#pragma unroll
        for (int kx = 0; kx < 4; kx++) {
            const int off = (((2 * kx + (tig >> 1)) ^ g) << 4) + 8 * (tig & 1);
            uint2 ua0[4], ua1[4], ub[NJ];
#pragma unroll
            for (int i = 0; i < 4; i++) {
                ua0[i] = *(const uint2*)(stg + aRow + i * 2048 + off);
                ua1[i] = *(const uint2*)(stg + aRow + i * 2048 + 1024 + off);
            }
#pragma unroll
            for (int j = 0; j < NJ; j++)
                ub[j] = *(const uint2*)(stg + bRow + j * 1024 + off);
#pragma unroll
            for (int i = 0; i < 4; i++)
#pragma unroll
                for (int j = 0; j < NJ; j++)
                    mma_f16(c[i][j], ua0[i].x, ua1[i].x, ua0[i].y, ua1[i].y,
                            ub[j].x, ub[j].y);
        }
    }

    // ---- epilogue ----
#pragma unroll
    for (int i = 0; i < 4; i++) {
#pragma unroll
        for (int half = 0; half < 2; half++) {
            int mrow = m_base + wm + 16 * i + g + half * 8;
            if (mrow >= cnt) continue;
            if (MODE == 0) {
                __half* hp = g_hh + (size_t)(hoff + mrow) * H_DIM + n_base;
#pragma unroll
                for (int j = 0; j < NJ; j++) {
                    int col = wn + j * 8 + tig * 2;
                    float v0 = c[i][j][half * 2 + 0] + sBias[col];
                    float v1 = c[i][j][half * 2 + 1] + sBias[col + 1];
                    int col2 = (col & ~15) + kslot(col & 15);   // permuted store
                    *reinterpret_cast<__half2*>(hp + col2) =
                        __floats2half2_rn(gelu_exact(v0), gelu_exact(v1));
                }
            } else {
                float* yp = g_y + (size_t)(hoff + mrow) * D_DIM + n_base;
#pragma unroll
                for (int j = 0; j < NJ; j++) {
                    int col = wn + j * 8 + tig * 2;
                    float v0 = c[i][j][half * 2 + 0] + sBias[col];
                    float v1 = c[i][j][half * 2 + 1] + sBias[col + 1];
                    *reinterpret_cast<float2*>(yp + col) = make_float2(v0, v1);
                }
            }
        }
    }
}

// ---------------- LayerNorm ----------------
__global__ void ln_k(const float* __restrict__ x,
                     const float* __restrict__ gamma,
                     const float* __restrict__ beta,
                     float* __restrict__ out) {
    int t = blockIdx.x;
    int tid = threadIdx.x;
    int lane = tid & 31, wid = tid >> 5;

    int i0 = g_inv[t * 2 + 0], i1 = g_inv[t * 2 + 1];
    float gt0 = g_gate[i0], gt1 = g_gate[i1];
    size_t r0 = (size_t)(g_off[i0 >> 13] + (i0 & (CAP - 1)));
    size_t r1 = (size_t)(g_off[i1 >> 13] + (i1 & (CAP - 1)));
    const float* y0 = g_y + r0 * D_DIM;
    const float* y1 = g_y + r1 * D_DIM;
    const float* xr = x + (size_t)t * D_DIM;

    int c = tid * 4;
    float4 xv = *reinterpret_cast<const float4*>(xr + c);
    float4 av = *reinterpret_cast<const float4*>(y0 + c);
    float4 bv = *reinterpret_cast<const float4*>(y1 + c);
    float z0 = xv.x + gt0 * av.x + gt1 * bv.x;
    float z1 = xv.y + gt0 * av.y + gt1 * bv.y;
    float z2 = xv.z + gt0 * av.z + gt1 * bv.z;
    float z3 = xv.w + gt0 * av.w + gt1 * bv.w;

    float s  = z0 + z1 + z2 + z3;
    float sq = z0 * z0 + z1 * z1 + z2 * z2 + z3 * z3;
#pragma unroll
    for (int o = 16; o; o >>= 1) {
        s  += __shfl_xor_sync(0xffffffffu, s, o);
        sq += __shfl_xor_sync(0xffffffffu, sq, o);
    }
    __shared__ float ws[8], wq[8];
    if (lane == 0) { ws[wid] = s; wq[wid] = sq; }
    __syncthreads();
    if (wid == 0) {
        float s2 = (lane < 8) ? ws[lane] : 0.f;
        float q2 = (lane < 8) ? wq[lane] : 0.f;
#pragma unroll
        for (int o = 4; o; o >>= 1) {
            s2 += __shfl_xor_sync(0xffffffffu, s2, o);
            q2 += __shfl_xor_sync(0xffffffffu, q2, o);
        }
        if (lane == 0) { ws[0] = s2; wq[0] = q2; }
    }
    __syncthreads();
    float mu  = ws[0] * (1.0f / D_DIM);
    float var = wq[0] * (1.0f / D_DIM) - mu * mu;
    float inv = rsqrtf(var + 1e-5f);

    float4 gm = *reinterpret_cast<const float4*>(gamma + c);
    float4 bt = *reinterpret_cast<const float4*>(beta + c);
    float4 o;
    o.x = (z0 - mu) * inv * gm.x + bt.x;
    o.y = (z1 - mu) * inv * gm.y + bt.y;
    o.z = (z2 - mu) * inv * gm.z + bt.z;
    o.w = (z3 - mu) * inv * gm.w + bt.w;
    *reinterpret_cast<float4*>(out + (size_t)t * D_DIM + c) = o;
}

// ---------------- launch ----------------
extern "C" void kernel_launch(void* const* d_in, const int* in_sizes, int n_in,
                              void* d_out, int out_size) {
    (void)in_sizes; (void)n_in; (void)out_size;
    const float* x     = (const float*)d_in[0];
    const float* gW    = (const float*)d_in[1];
    const float* gb    = (const float*)d_in[2];
    const float* W1    = (const float*)d_in[3];
    const float* b1    = (const float*)d_in[4];
    const float* W2    = (const float*)d_in[5];
    const float* b2    = (const float*)d_in[6];
    const float* gamma = (const float*)d_in[7];
    const float* beta  = (const float*)d_in[8];
    float* out = (float*)d_out;

    const int S0 = 1024 + NSTAGE * (A_BYTES + 256 * 128);  // 197632
    const int S1 = 1024 + NSTAGE * (A_BYTES + 128 * 128);  // 132096
    cudaFuncSetAttribute((const void*)gemm_h<0>,
                         cudaFuncAttributeMaxDynamicSharedMemorySize, S0);
    cudaFuncSetAttribute((const void*)gemm_h<1>,
                         cudaFuncAttributeMaxDynamicSharedMemorySize, S1);

    __half* w1h; cudaGetSymbolAddress((void**)&w1h, g_w1h);
    __half* w2h; cudaGetSymbolAddress((void**)&w2h, g_w2h);

    reset_k<<<1, 32>>>();
    router_k<<<N_TOK / 8, 256>>>(x, gW, gb);
    tail_k<<<1, 1>>>(out + (size_t)N_TOK * D_DIM);
    wtrans_k<<<dim3(H_DIM / 64, D_DIM / 64, E_NUM), 256>>>(W1, w1h, D_DIM, H_DIM);
    wtrans_k<<<dim3(D_DIM / 64, H_DIM / 64, E_NUM), 256>>>(W2, w2h, H_DIM, D_DIM);
    gemm_h<0><<<dim3(H_DIM / 256, CAP / BM, E_NUM), 256, S0>>>(b1);
    gemm_h<1><<<dim3(D_DIM / 128, CAP / BM, E_NUM), 256, S1>>>(b2);
    ln_k<<<N_TOK, 256>>>(x, gamma, beta, out);
}

// round 8
// speedup vs baseline: 1.0514x; 1.0514x over previous
#include <cuda_runtime.h>
#include <cuda_fp16.h>
#include <math.h>
#include <stdint.h>

#define D_DIM 1024
#define H_DIM 2048
#define E_NUM 8
#define CAP   8192
#define N_TOK 8192
#define BM 128
#define BN 256
#define BK 64                            // halves per slab = 128 B rows

#define A_BYTES 16384                    // 128 rows x 128B
#define B_BYTES 32768                    // 256 rows x 128B
#define STAGE_BYTES (A_BYTES + B_BYTES)  // 49152
#define NSTAGE 4
#define SMEM_TOTAL (1024 + NSTAGE * STAGE_BYTES)  // 197632

// ---------------- device scratch ----------------
__device__ int    g_cnt[E_NUM];
__device__ int    g_off[E_NUM];
__device__ int    g_tok[E_NUM * CAP];
__device__ float  g_gate[E_NUM * CAP];
__device__ int    g_inv[N_TOK * 2];
__device__ float  g_imp[E_NUM];
__device__ float  g_ent;
__device__ __half g_xh[(size_t)N_TOK * D_DIM];            // x as half, k-permuted
__device__ __half g_hh[(size_t)N_TOK * 2 * H_DIM];        // h as half, k-permuted
__device__ __half g_yh[(size_t)N_TOK * 2 * D_DIM];        // gate*y as half
__device__ __half g_w1h[(size_t)E_NUM * H_DIM * D_DIM];   // [e][n=H][k'=D]
__device__ __half g_w2h[(size_t)E_NUM * D_DIM * H_DIM];   // [e][n=D][k'=H]

// k-group permutation: storage slot s holds source k = KORD[s]
__device__ __constant__ int KORD[16] = {0,1,8,9,2,3,10,11,4,5,12,13,6,7,14,15};
__device__ __forceinline__ int kslot(int r) {      // r = k & 15, even
    return (((r >> 1) & 3) << 2) + ((r >> 3) << 1);
}

// ---------------- helpers ----------------
__device__ __forceinline__ uint32_t smem_u32(const void* p) {
    uint32_t a;
    asm("{ .reg .u64 t; cvta.to.shared.u64 t, %1; cvt.u32.u64 %0, t; }" : "=r"(a) : "l"(p));
    return a;
}
#define CP16(dst, src) \
    asm volatile("cp.async.cg.shared.global [%0], [%1], 16;" :: "r"(dst), "l"(src))
#define CP_COMMIT()  asm volatile("cp.async.commit_group;" ::: "memory")
#define CP_WAIT(n)   asm volatile("cp.async.wait_group %0;" :: "n"(n) : "memory")

__device__ __forceinline__ void mma_f16(float* c, unsigned a0, unsigned a1,
                                        unsigned a2, unsigned a3,
                                        unsigned b0, unsigned b1) {
    asm volatile(
        "mma.sync.aligned.m16n8k16.row.col.f32.f16.f16.f32 "
        "{%0,%1,%2,%3}, {%4,%5,%6,%7}, {%8,%9}, {%0,%1,%2,%3};\n"
        : "+f"(c[0]), "+f"(c[1]), "+f"(c[2]), "+f"(c[3])
        : "r"(a0), "r"(a1), "r"(a2), "r"(a3), "r"(b0), "r"(b1));
}
__device__ __forceinline__ float gelu_exact(float v) {
    return 0.5f * v * (1.0f + erff(v * 0.70710678118654752440f));
}

// ---------------- small kernels ----------------
__global__ void reset_k() {
    int t = threadIdx.x;
    if (t < E_NUM) { g_cnt[t] = 0; g_imp[t] = 0.0f; }
    if (t == 0)    g_ent = 0.0f;
}

// router + x->half conversion fused (warp per token)
__global__ void router_k(const float* __restrict__ x,
                         const float* __restrict__ gW,
                         const float* __restrict__ gb) {
    int token = (blockIdx.x * blockDim.x + threadIdx.x) >> 5;
    int lane  = threadIdx.x & 31;
    if (token >= N_TOK) return;
    const float* xr = x + (size_t)token * D_DIM;
    __half* xh = g_xh + (size_t)token * D_DIM;

    float acc[8] = {0.f,0.f,0.f,0.f,0.f,0.f,0.f,0.f};
#pragma unroll
    for (int i = 0; i < 8; i++) {
        int d = lane * 4 + 128 * i;
        float4 xv = *reinterpret_cast<const float4*>(xr + d);
        int base = d & ~15, r = d & 15;
        *reinterpret_cast<__half2*>(xh + base + kslot(r)) =
            __floats2half2_rn(xv.x, xv.y);
        *reinterpret_cast<__half2*>(xh + base + kslot(r + 2)) =
            __floats2half2_rn(xv.z, xv.w);
        const float4* w = reinterpret_cast<const float4*>(gW + (size_t)d * E_NUM);
        float xs[4] = {xv.x, xv.y, xv.z, xv.w};
#pragma unroll
        for (int q = 0; q < 4; q++) {
            float4 wa = w[q * 2], wb = w[q * 2 + 1];
            acc[0] += xs[q] * wa.x; acc[1] += xs[q] * wa.y;
            acc[2] += xs[q] * wa.z; acc[3] += xs[q] * wa.w;
            acc[4] += xs[q] * wb.x; acc[5] += xs[q] * wb.y;
            acc[6] += xs[q] * wb.z; acc[7] += xs[q] * wb.w;
        }
    }
#pragma unroll
    for (int e = 0; e < 8; e++)
#pragma unroll
        for (int o = 16; o; o >>= 1) acc[e] += __shfl_xor_sync(0xffffffffu, acc[e], o);
    if (lane) return;

    float lg[8];
#pragma unroll
    for (int e = 0; e < 8; e++) lg[e] = acc[e] + gb[e];
    float mx = lg[0];
#pragma unroll
    for (int e = 1; e < 8; e++) mx = fmaxf(mx, lg[e]);
    float p[8], Z = 0.f;
#pragma unroll
    for (int e = 0; e < 8; e++) { p[e] = expf(lg[e] - mx); Z += p[e]; }
    float ent = 0.f;
#pragma unroll
    for (int e = 0; e < 8; e++) {
        p[e] /= Z;
        ent -= p[e] * logf(p[e] + 1e-8f);
        atomicAdd(&g_imp[e], p[e]);
    }
    atomicAdd(&g_ent, ent);

    int e0 = 0;
#pragma unroll
    for (int e = 1; e < 8; e++) if (lg[e] > lg[e0]) e0 = e;
    int e1 = -1;
#pragma unroll
    for (int e = 0; e < 8; e++) if (e != e0 && (e1 < 0 || lg[e] > lg[e1])) e1 = e;

    float dlt = expf(lg[e1] - lg[e0]);
    float g0 = 1.0f / (1.0f + dlt);
    float g1 = dlt / (1.0f + dlt);

    int s0 = atomicAdd(&g_cnt[e0], 1);
    g_tok[e0 * CAP + s0] = token; g_gate[e0 * CAP + s0] = g0;
    int s1 = atomicAdd(&g_cnt[e1], 1);
    g_tok[e1 * CAP + s1] = token; g_gate[e1 * CAP + s1] = g1;
    g_inv[token * 2 + 0] = e0 * CAP + s0;
    g_inv[token * 2 + 1] = e1 * CAP + s1;
}

__global__ void tail_k(float* __restrict__ out_tail) {
    if (threadIdx.x != 0 || blockIdx.x != 0) return;
    int off = 0;
    float loadv[8], impv[8];
    for (int e = 0; e < 8; e++) { g_off[e] = off; off += g_cnt[e]; }
    for (int e = 0; e < 8; e++) {
        loadv[e] = (float)g_cnt[e] / (float)N_TOK;
        impv[e]  = g_imp[e] / (float)N_TOK;
    }
    float bal = 0.f, util = 0.f;
    for (int e = 0; e < 8; e++) bal += impv[e] * loadv[e];
    bal *= (float)E_NUM;
    for (int e = 0; e < 8; e++) util -= loadv[e] * logf(loadv[e] + 1e-8f);
    out_tail[0] = bal;
    out_tail[1] = g_ent / (float)N_TOK;
    out_tail[2] = util;
    for (int e = 0; e < 8; e++) out_tail[3 + e]  = loadv[e];
    for (int e = 0; e < 8; e++) out_tail[11 + e] = impv[e];
}

// W[e][k][n] fp32 -> WT[e][n][k'] half. 64x64 tiles, full-line half writes.
__global__ void wtrans_k(const float* __restrict__ W, __half* __restrict__ WT,
                         int K, int N) {
    __shared__ float t[64][68];
    int e = blockIdx.z, n0 = blockIdx.x * 64, k0 = blockIdx.y * 64;
    const float* Ws = W + (size_t)e * K * N + (size_t)k0 * N + n0;
    __half* Wd = WT + (size_t)e * N * K;
#pragma unroll
    for (int i = 0; i < 4; i++) {
        int idx = threadIdx.x + 256 * i;     // 0..1023
        int kr = idx >> 4, c4 = idx & 15;
        float4 v = *reinterpret_cast<const float4*>(Ws + (size_t)kr * N + c4 * 4);
        *reinterpret_cast<float4*>(&t[kr][c4 * 4]) = v;
    }
    __syncthreads();
    int n = threadIdx.x >> 2, kg = (threadIdx.x & 3) * 16;
    __half hh[16];
#pragma unroll
    for (int s = 0; s < 16; s++) hh[s] = __float2half(t[kg + KORD[s]][n]);
    __half* drow = Wd + (size_t)(n0 + n) * K + k0 + kg;
    *reinterpret_cast<uint4*>(drow)     = *reinterpret_cast<uint4*>(hh);
    *reinterpret_cast<uint4*>(drow + 8) = *reinterpret_cast<uint4*>(hh + 8);
}

// ---------------- fp16 pipelined grouped GEMM (128x256, warp 64x64, BK=64) ----------------
// MODE 0: A = gather(g_xh) [K=1024], B=g_w1h, bias+gelu -> g_hh (half, permuted)
// MODE 1: A = g_hh [K=2048], B=g_w2h, gate*(bias+c) -> g_yh (half)
template <int MODE>
__global__ void __launch_bounds__(256, 1)
gemm_h(const float* __restrict__ bias) {
    constexpr int Kdim  = (MODE == 0) ? D_DIM : H_DIM;
    constexpr int Ncols = (MODE == 0) ? H_DIM : D_DIM;
    constexpr int NS    = Kdim / BK;

    extern __shared__ char smem[];
    const int e = blockIdx.z;
    const int cnt = g_cnt[e];
    const int m_base = blockIdx.y * BM;
    if (m_base >= cnt) return;
    const int n_base = blockIdx.x * BN;
    const int hoff = g_off[e];

    const int tid = threadIdx.x, wid = tid >> 5, lane = tid & 31;
    const int g = lane >> 2, tig = lane & 3;
    const int wm = (wid & 1) * 64;
    const int wn = (wid >> 1) * 64;
    const uint32_t sb = smem_u32(smem);
    float* sBias = (float*)smem;

    sBias[tid] = bias[(size_t)e * Ncols + n_base + tid];

    // ---- cp.async assignments ----
    const int cch = tid & 7;          // 16B chunk (8 halves) within 128B row
    const int r0  = tid >> 3;         // base row 0..31
    const __half* Ab = (MODE == 0) ? (const __half*)g_xh : (const __half*)g_hh;
    const __half* Wb = (MODE == 0) ? (const __half*)g_w1h : (const __half*)g_w2h;

    const __half* aSrc[4];
#pragma unroll
    for (int i = 0; i < 4; i++) {
        int am = m_base + r0 + 32 * i;
        if (am >= cnt) am = cnt - 1;
        size_t row = (MODE == 0) ? (size_t)g_tok[e * CAP + am] : (size_t)(hoff + am);
        aSrc[i] = Ab + row * Kdim + cch * 8;
    }
    const __half* bSrc = Wb + ((size_t)e * Ncols + n_base + r0) * Kdim + cch * 8;

    const uint32_t swz = (uint32_t)((cch ^ (r0 & 7)) << 4);
    const uint32_t aDst = sb + 1024 + r0 * 128 + swz;
    const uint32_t bDst = sb + 1024 + A_BYTES + r0 * 128 + swz;

    float c[4][8][4];
#pragma unroll
    for (int i = 0; i < 4; i++)
#pragma unroll
        for (int j = 0; j < 8; j++)
#pragma unroll
            for (int r = 0; r < 4; r++) c[i][j][r] = 0.f;

    auto issue = [&](int s) {
        if (s < NS) {
            const int kb = s * BK;
            const uint32_t so = (uint32_t)((s & (NSTAGE - 1)) * STAGE_BYTES);
#pragma unroll
            for (int i = 0; i < 4; i++)
                CP16(aDst + so + i * 4096, aSrc[i] + kb);
#pragma unroll
            for (int i = 0; i < 8; i++)
                CP16(bDst + so + i * 4096, bSrc + (size_t)(32 * i) * Kdim + kb);
        }
        CP_COMMIT();
    };

    issue(0); issue(1); issue(2);

    const int aRow = (wm + g) * 128;
    const int bRow = A_BYTES + (wn + g) * 128;

    for (int s = 0; s < NS; s++) {
        CP_WAIT(2);
        __syncthreads();
        issue(s + 3);

        const char* stg = smem + 1024 + (s & (NSTAGE - 1)) * STAGE_BYTES;
#pragma unroll
        for (int kx = 0; kx < 4; kx++) {
            const int off = (((2 * kx + (tig >> 1)) ^ g) << 4) + 8 * (tig & 1);
            uint2 ua0[4], ua1[4], ub[8];
#pragma unroll
            for (int i = 0; i < 4; i++) {
                ua0[i] = *(const uint2*)(stg + aRow + i * 2048 + off);
                ua1[i] = *(const uint2*)(stg + aRow + i * 2048 + 1024 + off);
            }
#pragma unroll
            for (int j = 0; j < 8; j++)
                ub[j] = *(const uint2*)(stg + bRow + j * 1024 + off);
#pragma unroll
            for (int i = 0; i < 4; i++)
#pragma unroll
                for (int j = 0; j < 8; j++)
                    mma_f16(c[i][j], ua0[i].x, ua1[i].x, ua0[i].y, ua1[i].y,
                            ub[j].x, ub[j].y);
        }
    }

    // ---- epilogue ----
#pragma unroll
    for (int i = 0; i < 4; i++) {
#pragma unroll
        for (int half = 0; half < 2; half++) {
            int mrow = m_base + wm + 16 * i + g + half * 8;
            if (mrow >= cnt) continue;
            if (MODE == 0) {
                __half* hp = g_hh + (size_t)(hoff + mrow) * H_DIM + n_base;
#pragma unroll
                for (int j = 0; j < 8; j++) {
                    int col = wn + j * 8 + tig * 2;
                    float v0 = c[i][j][half * 2 + 0] + sBias[col];
                    float v1 = c[i][j][half * 2 + 1] + sBias[col + 1];
                    int col2 = (col & ~15) + kslot(col & 15);   // permuted store
                    *reinterpret_cast<__half2*>(hp + col2) =
                        __floats2half2_rn(gelu_exact(v0), gelu_exact(v1));
                }
            } else {
                float gate = g_gate[e * CAP + mrow];
                __half* yp = g_yh + (size_t)(hoff + mrow) * D_DIM + n_base;
#pragma unroll
                for (int j = 0; j < 8; j++) {
                    int col = wn + j * 8 + tig * 2;
                    float v0 = gate * (c[i][j][half * 2 + 0] + sBias[col]);
                    float v1 = gate * (c[i][j][half * 2 + 1] + sBias[col + 1]);
                    *reinterpret_cast<__half2*>(yp + col) = __floats2half2_rn(v0, v1);
                }
            }
        }
    }
}

// ---------------- LayerNorm (y pre-gated, fp16) ----------------
__global__ void ln_k(const float* __restrict__ x,
                     const float* __restrict__ gamma,
                     const float* __restrict__ beta,
                     float* __restrict__ out) {
    int t = blockIdx.x;
    int tid = threadIdx.x;
    int lane = tid & 31, wid = tid >> 5;

    int i0 = g_inv[t * 2 + 0], i1 = g_inv[t * 2 + 1];
    size_t r0 = (size_t)(g_off[i0 >> 13] + (i0 & (CAP - 1)));
    size_t r1 = (size_t)(g_off[i1 >> 13] + (i1 & (CAP - 1)));
    const __half* y0 = g_yh + r0 * D_DIM;
    const __half* y1 = g_yh + r1 * D_DIM;
    const float* xr = x + (size_t)t * D_DIM;

    int c = tid * 4;
    float4 xv = *reinterpret_cast<const float4*>(xr + c);
    __half2 a01 = *reinterpret_cast<const __half2*>(y0 + c);
    __half2 a23 = *reinterpret_cast<const __half2*>(y0 + c + 2);
    __half2 b01 = *reinterpret_cast<const __half2*>(y1 + c);
    __half2 b23 = *reinterpret_cast<const __half2*>(y1 + c + 2);
    float2 fa01 = __half22float2(a01), fa23 = __half22float2(a23);
    float2 fb01 = __half22float2(b01), fb23 = __half22float2(b23);
    float z0 = xv.x + fa01.x + fb01.x;
    float z1 = xv.y + fa01.y + fb01.y;
    float z2 = xv.z + fa23.x + fb23.x;
    float z3 = xv.w + fa23.y + fb23.y;

    float s  = z0 + z1 + z2 + z3;
    float sq = z0 * z0 + z1 * z1 + z2 * z2 + z3 * z3;
#pragma unroll
    for (int o = 16; o; o >>= 1) {
        s  += __shfl_xor_sync(0xffffffffu, s, o);
        sq += __shfl_xor_sync(0xffffffffu, sq, o);
    }
    __shared__ float ws[8], wq[8];
    if (lane == 0) { ws[wid] = s; wq[wid] = sq; }
    __syncthreads();
    if (wid == 0) {
        float s2 = (lane < 8) ? ws[lane] : 0.f;
        float q2 = (lane < 8) ? wq[lane] : 0.f;
#pragma unroll
        for (int o = 4; o; o >>= 1) {
            s2 += __shfl_xor_sync(0xffffffffu, s2, o);
            q2 += __shfl_xor_sync(0xffffffffu, q2, o);
        }
        if (lane == 0) { ws[0] = s2; wq[0] = q2; }
    }
    __syncthreads();
    float mu  = ws[0] * (1.0f / D_DIM);
    float var = wq[0] * (1.0f / D_DIM) - mu * mu;
    float inv = rsqrtf(var + 1e-5f);

    float4 gm = *reinterpret_cast<const float4*>(gamma + c);
    float4 bt = *reinterpret_cast<const float4*>(beta + c);
    float4 o;
    o.x = (z0 - mu) * inv * gm.x + bt.x;
    o.y = (z1 - mu) * inv * gm.y + bt.y;
    o.z = (z2 - mu) * inv * gm.z + bt.z;
    o.w = (z3 - mu) * inv * gm.w + bt.w;
    *reinterpret_cast<float4*>(out + (size_t)t * D_DIM + c) = o;
}

// ---------------- launch ----------------
extern "C" void kernel_launch(void* const* d_in, const int* in_sizes, int n_in,
                              void* d_out, int out_size) {
    (void)in_sizes; (void)n_in; (void)out_size;
    const float* x     = (const float*)d_in[0];
    const float* gW    = (const float*)d_in[1];
    const float* gb    = (const float*)d_in[2];
    const float* W1    = (const float*)d_in[3];
    const float* b1    = (const float*)d_in[4];
    const float* W2    = (const float*)d_in[5];
    const float* b2    = (const float*)d_in[6];
    const float* gamma = (const float*)d_in[7];
    const float* beta  = (const float*)d_in[8];
    float* out = (float*)d_out;

    cudaFuncSetAttribute((const void*)gemm_h<0>,
                         cudaFuncAttributeMaxDynamicSharedMemorySize, SMEM_TOTAL);
    cudaFuncSetAttribute((const void*)gemm_h<1>,
                         cudaFuncAttributeMaxDynamicSharedMemorySize, SMEM_TOTAL);

    __half* w1h; cudaGetSymbolAddress((void**)&w1h, g_w1h);
    __half* w2h; cudaGetSymbolAddress((void**)&w2h, g_w2h);

    reset_k<<<1, 32>>>();
    router_k<<<N_TOK / 8, 256>>>(x, gW, gb);
    tail_k<<<1, 1>>>(out + (size_t)N_TOK * D_DIM);
    wtrans_k<<<dim3(H_DIM / 64, D_DIM / 64, E_NUM), 256>>>(W1, w1h, D_DIM, H_DIM);
    wtrans_k<<<dim3(D_DIM / 64, H_DIM / 64, E_NUM), 256>>>(W2, w2h, H_DIM, D_DIM);
    gemm_h<0><<<dim3(H_DIM / BN, CAP / BM, E_NUM), 256, SMEM_TOTAL>>>(b1);
    gemm_h<1><<<dim3(D_DIM / BN, CAP / BM, E_NUM), 256, SMEM_TOTAL>>>(b2);
    ln_k<<<N_TOK, 256>>>(x, gamma, beta, out);
}

// round 9
// speedup vs baseline: 1.0816x; 1.0287x over previous
#include <cuda_runtime.h>
#include <cuda_fp16.h>
#include <math.h>
#include <stdint.h>

#define D_DIM 1024
#define H_DIM 2048
#define E_NUM 8
#define CAP   8192
#define N_TOK 8192
#define BM 128
#define BN 256
#define BK 64                            // halves per slab = 128 B rows

#define A_BYTES 16384                    // 128 rows x 128B
#define B_BYTES 32768                    // 256 rows x 128B
#define STAGE_BYTES (A_BYTES + B_BYTES)  // 49152
#define NSTAGE 4
#define SMEM_TOTAL (1024 + NSTAGE * STAGE_BYTES)  // 197632

// ---------------- device scratch ----------------
__device__ int    g_cnt[E_NUM];
__device__ int    g_off[E_NUM];
__device__ int    g_tok[E_NUM * CAP];
__device__ float  g_gate[E_NUM * CAP];
__device__ int    g_inv[N_TOK * 2];
__device__ float  g_imp[E_NUM];
__device__ float  g_ent;
__device__ __half g_xh[(size_t)N_TOK * D_DIM];            // x as half, k-permuted
__device__ __half g_hh[(size_t)N_TOK * 2 * H_DIM];        // h as half, k-permuted
__device__ __half g_yh[(size_t)N_TOK * 2 * D_DIM];        // gate*y as half
__device__ __half g_w1h[(size_t)E_NUM * H_DIM * D_DIM];   // [e][n=H][k'=D]
__device__ __half g_w2h[(size_t)E_NUM * D_DIM * H_DIM];   // [e][n=D][k'=H]

// k-group permutation: storage slot s holds source k = KORD[s]
__device__ __constant__ int KORD[16] = {0,1,8,9,2,3,10,11,4,5,12,13,6,7,14,15};
__device__ __forceinline__ int kslot(int r) {      // r = k & 15, even
    return (((r >> 1) & 3) << 2) + ((r >> 3) << 1);
}

// ---------------- helpers ----------------
__device__ __forceinline__ uint32_t smem_u32(const void* p) {
    uint32_t a;
    asm("{ .reg .u64 t; cvta.to.shared.u64 t, %1; cvt.u32.u64 %0, t; }" : "=r"(a) : "l"(p));
    return a;
}
#define CP16(dst, src) \
    asm volatile("cp.async.cg.shared.global [%0], [%1], 16;" :: "r"(dst), "l"(src))
#define CP_COMMIT()  asm volatile("cp.async.commit_group;" ::: "memory")
#define CP_WAIT(n)   asm volatile("cp.async.wait_group %0;" :: "n"(n) : "memory")

__device__ __forceinline__ void mma_f16(float* c, unsigned a0, unsigned a1,
                                        unsigned a2, unsigned a3,
                                        unsigned b0, unsigned b1) {
    asm volatile(
        "mma.sync.aligned.m16n8k16.row.col.f32.f16.f16.f32 "
        "{%0,%1,%2,%3}, {%4,%5,%6,%7}, {%8,%9}, {%0,%1,%2,%3};\n"
        : "+f"(c[0]), "+f"(c[1]), "+f"(c[2]), "+f"(c[3])
        : "r"(a0), "r"(a1), "r"(a2), "r"(a3), "r"(b0), "r"(b1));
}
__device__ __forceinline__ float gelu_exact(float v) {
    return 0.5f * v * (1.0f + erff(v * 0.70710678118654752440f));
}

// ---------------- small kernels ----------------
__global__ void reset_k() {
    int t = threadIdx.x;
    if (t < E_NUM) { g_cnt[t] = 0; g_imp[t] = 0.0f; }
    if (t == 0)    g_ent = 0.0f;
}

// router + x->half conversion fused (warp per token, gW staged in smem)
__global__ void router_k(const float* __restrict__ x,
                         const float* __restrict__ gW,
                         const float* __restrict__ gb) {
    __shared__ float4 sgW[2048];        // 32 KB, 16B-swizzled
    int tid = threadIdx.x;
    for (int s = tid; s < 2048; s += 256)
        sgW[s ^ ((s >> 3) & 7)] = reinterpret_cast<const float4*>(gW)[s];
    __syncthreads();

    int token = (blockIdx.x * blockDim.x + tid) >> 5;
    int lane  = tid & 31;
    if (token >= N_TOK) return;
    const float* xr = x + (size_t)token * D_DIM;
    __half* xh = g_xh + (size_t)token * D_DIM;

    float acc[8] = {0.f,0.f,0.f,0.f,0.f,0.f,0.f,0.f};
#pragma unroll
    for (int i = 0; i < 8; i++) {
        int d = lane * 4 + 128 * i;
        float4 xv = *reinterpret_cast<const float4*>(xr + d);
        int base = d & ~15, r = d & 15;
        *reinterpret_cast<__half2*>(xh + base + kslot(r)) =
            __floats2half2_rn(xv.x, xv.y);
        *reinterpret_cast<__half2*>(xh + base + kslot(r + 2)) =
            __floats2half2_rn(xv.z, xv.w);
        float xs[4] = {xv.x, xv.y, xv.z, xv.w};
#pragma unroll
        for (int q = 0; q < 4; q++) {
            int s0 = (d + q) * 2;
            float4 wa = sgW[s0 ^ ((s0 >> 3) & 7)];
            int s1 = s0 + 1;
            float4 wb = sgW[s1 ^ ((s1 >> 3) & 7)];
            acc[0] += xs[q] * wa.x; acc[1] += xs[q] * wa.y;
            acc[2] += xs[q] * wa.z; acc[3] += xs[q] * wa.w;
            acc[4] += xs[q] * wb.x; acc[5] += xs[q] * wb.y;
            acc[6] += xs[q] * wb.z; acc[7] += xs[q] * wb.w;
        }
    }
#pragma unroll
    for (int e = 0; e < 8; e++)
#pragma unroll
        for (int o = 16; o; o >>= 1) acc[e] += __shfl_xor_sync(0xffffffffu, acc[e], o);
    if (lane) return;

    float lg[8];
#pragma unroll
    for (int e = 0; e < 8; e++) lg[e] = acc[e] + gb[e];
    float mx = lg[0];
#pragma unroll
    for (int e = 1; e < 8; e++) mx = fmaxf(mx, lg[e]);
    float p[8], Z = 0.f;
#pragma unroll
    for (int e = 0; e < 8; e++) { p[e] = expf(lg[e] - mx); Z += p[e]; }
    float ent = 0.f;
#pragma unroll
    for (int e = 0; e < 8; e++) {
        p[e] /= Z;
        ent -= p[e] * logf(p[e] + 1e-8f);
        atomicAdd(&g_imp[e], p[e]);
    }
    atomicAdd(&g_ent, ent);

    int e0 = 0;
#pragma unroll
    for (int e = 1; e < 8; e++) if (lg[e] > lg[e0]) e0 = e;
    int e1 = -1;
#pragma unroll
    for (int e = 0; e < 8; e++) if (e != e0 && (e1 < 0 || lg[e] > lg[e1])) e1 = e;

    float dlt = expf(lg[e1] - lg[e0]);
    float g0 = 1.0f / (1.0f + dlt);
    float g1 = dlt / (1.0f + dlt);

    int s0 = atomicAdd(&g_cnt[e0], 1);
    g_tok[e0 * CAP + s0] = token; g_gate[e0 * CAP + s0] = g0;
    int s1 = atomicAdd(&g_cnt[e1], 1);
    g_tok[e1 * CAP + s1] = token; g_gate[e1 * CAP + s1] = g1;
    g_inv[token * 2 + 0] = e0 * CAP + s0;
    g_inv[token * 2 + 1] = e1 * CAP + s1;
}

__global__ void tail_k(float* __restrict__ out_tail) {
    if (threadIdx.x != 0 || blockIdx.x != 0) return;
    int off = 0;
    float loadv[8], impv[8];
    for (int e = 0; e < 8; e++) { g_off[e] = off; off += g_cnt[e]; }
    for (int e = 0; e < 8; e++) {
        loadv[e] = (float)g_cnt[e] / (float)N_TOK;
        impv[e]  = g_imp[e] / (float)N_TOK;
    }
    float bal = 0.f, util = 0.f;
    for (int e = 0; e < 8; e++) bal += impv[e] * loadv[e];
    bal *= (float)E_NUM;
    for (int e = 0; e < 8; e++) util -= loadv[e] * logf(loadv[e] + 1e-8f);
    out_tail[0] = bal;
    out_tail[1] = g_ent / (float)N_TOK;
    out_tail[2] = util;
    for (int e = 0; e < 8; e++) out_tail[3 + e]  = loadv[e];
    for (int e = 0; e < 8; e++) out_tail[11 + e] = impv[e];
}

// W[e][k][n] fp32 -> WT[e][n][k'] half. 64x64 tiles; conflict-free readout.
__global__ void wtrans_k(const float* __restrict__ W, __half* __restrict__ WT,
                         int K, int N) {
    __shared__ float t[64][68];
    int e = blockIdx.z, n0 = blockIdx.x * 64, k0 = blockIdx.y * 64;
    const float* Ws = W + (size_t)e * K * N + (size_t)k0 * N + n0;
    __half* Wd = WT + (size_t)e * N * K;
#pragma unroll
    for (int i = 0; i < 4; i++) {
        int idx = threadIdx.x + 256 * i;     // 0..1023
        int kr = idx >> 4, c4 = idx & 15;
        float4 v = *reinterpret_cast<const float4*>(Ws + (size_t)kr * N + c4 * 4);
        *reinterpret_cast<float4*>(&t[kr][c4 * 4]) = v;
    }
    __syncthreads();
    // warp = 32 consecutive n, one kg -> conflict-free smem reads
    int n = threadIdx.x & 63, kg = (threadIdx.x >> 6) * 16;
    __half hh[16];
#pragma unroll
    for (int s = 0; s < 16; s++) hh[s] = __float2half(t[kg + KORD[s]][n]);
    __half* drow = Wd + (size_t)(n0 + n) * K + k0 + kg;
    *reinterpret_cast<uint4*>(drow)     = *reinterpret_cast<uint4*>(hh);
    *reinterpret_cast<uint4*>(drow + 8) = *reinterpret_cast<uint4*>(hh + 8);
}

// ---------------- fp16 pipelined grouped GEMM (128x256, warp 64x64, BK=64) ----------------
// MODE 0: A = gather(g_xh) [K=1024], B=g_w1h, bias+gelu -> g_hh (half, permuted)
// MODE 1: A = g_hh [K=2048], B=g_w2h, gate*(bias+c) -> g_yh (half)
template <int MODE>
__global__ void __launch_bounds__(256, 1)
gemm_h(const float* __restrict__ bias) {
    constexpr int Kdim  = (MODE == 0) ? D_DIM : H_DIM;
    constexpr int Ncols = (MODE == 0) ? H_DIM : D_DIM;
    constexpr int NS    = Kdim / BK;

    extern __shared__ char smem[];
    const int e = blockIdx.z;
    const int cnt = g_cnt[e];
    const int m_base = blockIdx.y * BM;
    if (m_base >= cnt) return;
    const int n_base = blockIdx.x * BN;
    const int hoff = g_off[e];

    const int tid = threadIdx.x, wid = tid >> 5, lane = tid & 31;
    const int g = lane >> 2, tig = lane & 3;
    const int wm = (wid & 1) * 64;
    const int wn = (wid >> 1) * 64;
    const uint32_t sb = smem_u32(smem);
    float* sBias = (float*)smem;

    sBias[tid] = bias[(size_t)e * Ncols + n_base + tid];

    // ---- cp.async assignments ----
    const int cch = tid & 7;          // 16B chunk (8 halves) within 128B row
    const int r0  = tid >> 3;         // base row 0..31
    const __half* Ab = (MODE == 0) ? (const __half*)g_xh : (const __half*)g_hh;
    const __half* Wb = (MODE == 0) ? (const __half*)g_w1h : (const __half*)g_w2h;

    const __half* aSrc[4];
#pragma unroll
    for (int i = 0; i < 4; i++) {
        int am = m_base + r0 + 32 * i;
        if (am >= cnt) am = cnt - 1;
        size_t row = (MODE == 0) ? (size_t)g_tok[e * CAP + am] : (size_t)(hoff + am);
        aSrc[i] = Ab + row * Kdim + cch * 8;
    }
    const __half* bSrc = Wb + ((size_t)e * Ncols + n_base + r0) * Kdim + cch * 8;

    const uint32_t swz = (uint32_t)((cch ^ (r0 & 7)) << 4);
    const uint32_t aDst = sb + 1024 + r0 * 128 + swz;
    const uint32_t bDst = sb + 1024 + A_BYTES + r0 * 128 + swz;

    float c[4][8][4];
#pragma unroll
    for (int i = 0; i < 4; i++)
#pragma unroll
        for (int j = 0; j < 8; j++)
#pragma unroll
            for (int r = 0; r < 4; r++) c[i][j][r] = 0.f;

    auto issue = [&](int s) {
        if (s < NS) {
            const int kb = s * BK;
            const uint32_t so = (uint32_t)((s & (NSTAGE - 1)) * STAGE_BYTES);
#pragma unroll
            for (int i = 0; i < 4; i++)
                CP16(aDst + so + i * 4096, aSrc[i] + kb);
#pragma unroll
            for (int i = 0; i < 8; i++)
                CP16(bDst + so + i * 4096, bSrc + (size_t)(32 * i) * Kdim + kb);
        }
        CP_COMMIT();
    };

    issue(0); issue(1); issue(2);

    const int aRow = (wm + g) * 128;
    const int bRow = A_BYTES + (wn + g) * 128;

    for (int s = 0; s < NS; s++) {
        CP_WAIT(2);
        __syncthreads();
        issue(s + 3);

        const char* stg = smem + 1024 + (s & (NSTAGE - 1)) * STAGE_BYTES;
#pragma unroll
        for (int kx = 0; kx < 4; kx++) {
            const int off = (((2 * kx + (tig >> 1)) ^ g) << 4) + 8 * (tig & 1);
            uint2 ua0[4], ua1[4], ub[8];
#pragma unroll
            for (int i = 0; i < 4; i++) {
                ua0[i] = *(const uint2*)(stg + aRow + i * 2048 + off);
                ua1[i] = *(const uint2*)(stg + aRow + i * 2048 + 1024 + off);
            }
#pragma unroll
            for (int j = 0; j < 8; j++)
                ub[j] = *(const uint2*)(stg + bRow + j * 1024 + off);
#pragma unroll
            for (int i = 0; i < 4; i++)
#pragma unroll
                for (int j = 0; j < 8; j++)
                    mma_f16(c[i][j], ua0[i].x, ua1[i].x, ua0[i].y, ua1[i].y,
                            ub[j].x, ub[j].y);
        }
    }

    // ---- epilogue ----
#pragma unroll
    for (int i = 0; i < 4; i++) {
#pragma unroll
        for (int half = 0; half < 2; half++) {
            int mrow = m_base + wm + 16 * i + g + half * 8;
            if (mrow >= cnt) continue;
            if (MODE == 0) {
                __half* hp = g_hh + (size_t)(hoff + mrow) * H_DIM + n_base;
#pragma unroll
                for (int j = 0; j < 8; j++) {
                    int col = wn + j * 8 + tig * 2;
                    float v0 = c[i][j][half * 2 + 0] + sBias[col];
                    float v1 = c[i][j][half * 2 + 1] + sBias[col + 1];
                    int col2 = (col & ~15) + kslot(col & 15);   // permuted store
                    *reinterpret_cast<__half2*>(hp + col2) =
                        __floats2half2_rn(gelu_exact(v0), gelu_exact(v1));
                }
            } else {
                float gate = g_gate[e * CAP + mrow];
                __half* yp = g_yh + (size_t)(hoff + mrow) * D_DIM + n_base;
#pragma unroll
                for (int j = 0; j < 8; j++) {
                    int col = wn + j * 8 + tig * 2;
                    float v0 = gate * (c[i][j][half * 2 + 0] + sBias[col]);
                    float v1 = gate * (c[i][j][half * 2 + 1] + sBias[col + 1]);
                    *reinterpret_cast<__half2*>(yp + col) = __floats2half2_rn(v0, v1);
                }
            }
        }
    }
}

// ---------------- LayerNorm (y pre-gated, fp16) ----------------
__global__ void ln_k(const float* __restrict__ x,
                     const float* __restrict__ gamma,
                     const float* __restrict__ beta,
                     float* __restrict__ out) {
    int t = blockIdx.x;
    int tid = threadIdx.x;
    int lane = tid & 31, wid = tid >> 5;

    int i0 = g_inv[t * 2 + 0], i1 = g_inv[t * 2 + 1];
    size_t r0 = (size_t)(g_off[i0 >> 13] + (i0 & (CAP - 1)));
    size_t r1 = (size_t)(g_off[i1 >> 13] + (i1 & (CAP - 1)));
    const __half* y0 = g_yh + r0 * D_DIM;
    const __half* y1 = g_yh + r1 * D_DIM;
    const float* xr = x + (size_t)t * D_DIM;

    int c = tid * 4;
    float4 xv = *reinterpret_cast<const float4*>(xr + c);
    __half2 a01 = *reinterpret_cast<const __half2*>(y0 + c);
    __half2 a23 = *reinterpret_cast<const __half2*>(y0 + c + 2);
    __half2 b01 = *reinterpret_cast<const __half2*>(y1 + c);
    __half2 b23 = *reinterpret_cast<const __half2*>(y1 + c + 2);
    float2 fa01 = __half22float2(a01), fa23 = __half22float2(a23);
    float2 fb01 = __half22float2(b01), fb23 = __half22float2(b23);
    float z0 = xv.x + fa01.x + fb01.x;
    float z1 = xv.y + fa01.y + fb01.y;
    float z2 = xv.z + fa23.x + fb23.x;
    float z3 = xv.w + fa23.y + fb23.y;

    float s  = z0 + z1 + z2 + z3;
    float sq = z0 * z0 + z1 * z1 + z2 * z2 + z3 * z3;
#pragma unroll
    for (int o = 16; o; o >>= 1) {
        s  += __shfl_xor_sync(0xffffffffu, s, o);
        sq += __shfl_xor_sync(0xffffffffu, sq, o);
    }
    __shared__ float ws[8], wq[8];
    if (lane == 0) { ws[wid] = s; wq[wid] = sq; }
    __syncthreads();
    if (wid == 0) {
        float s2 = (lane < 8) ? ws[lane] : 0.f;
        float q2 = (lane < 8) ? wq[lane] : 0.f;
#pragma unroll
        for (int o = 4; o; o >>= 1) {
            s2 += __shfl_xor_sync(0xffffffffu, s2, o);
            q2 += __shfl_xor_sync(0xffffffffu, q2, o);
        }
        if (lane == 0) { ws[0] = s2; wq[0] = q2; }
    }
    __syncthreads();
    float mu  = ws[0] * (1.0f / D_DIM);
    float var = wq[0] * (1.0f / D_DIM) - mu * mu;
    float inv = rsqrtf(var + 1e-5f);

    float4 gm = *reinterpret_cast<const float4*>(gamma + c);
    float4 bt = *reinterpret_cast<const float4*>(beta + c);
    float4 o;
    o.x = (z0 - mu) * inv * gm.x + bt.x;
    o.y = (z1 - mu) * inv * gm.y + bt.y;
    o.z = (z2 - mu) * inv * gm.z + bt.z;
    o.w = (z3 - mu) * inv * gm.w + bt.w;
    *reinterpret_cast<float4*>(out + (size_t)t * D_DIM + c) = o;
}

// ---------------- launch ----------------
extern "C" void kernel_launch(void* const* d_in, const int* in_sizes, int n_in,
                              void* d_out, int out_size) {
    (void)in_sizes; (void)n_in; (void)out_size;
    const float* x     = (const float*)d_in[0];
    const float* gW    = (const float*)d_in[1];
    const float* gb    = (const float*)d_in[2];
    const float* W1    = (const float*)d_in[3];
    const float* b1    = (const float*)d_in[4];
    const float* W2    = (const float*)d_in[5];
    const float* b2    = (const float*)d_in[6];
    const float* gamma = (const float*)d_in[7];
    const float* beta  = (const float*)d_in[8];
    float* out = (float*)d_out;

    cudaFuncSetAttribute((const void*)gemm_h<0>,
                         cudaFuncAttributeMaxDynamicSharedMemorySize, SMEM_TOTAL);
    cudaFuncSetAttribute((const void*)gemm_h<1>,
                         cudaFuncAttributeMaxDynamicSharedMemorySize, SMEM_TOTAL);

    __half* w1h; cudaGetSymbolAddress((void**)&w1h, g_w1h);
    __half* w2h; cudaGetSymbolAddress((void**)&w2h, g_w2h);

    reset_k<<<1, 32>>>();
    router_k<<<N_TOK / 8, 256>>>(x, gW, gb);
    tail_k<<<1, 1>>>(out + (size_t)N_TOK * D_DIM);
    wtrans_k<<<dim3(H_DIM / 64, D_DIM / 64, E_NUM), 256>>>(W1, w1h, D_DIM, H_DIM);
    wtrans_k<<<dim3(D_DIM / 64, H_DIM / 64, E_NUM), 256>>>(W2, w2h, H_DIM, D_DIM);
    gemm_h<0><<<dim3(H_DIM / BN, CAP / BM, E_NUM), 256, SMEM_TOTAL>>>(b1);
    gemm_h<1><<<dim3(D_DIM / BN, CAP / BM, E_NUM), 256, SMEM_TOTAL>>>(b2);
    ln_k<<<N_TOK, 256>>>(x, gamma, beta, out);
}

// round 10
// speedup vs baseline: 1.0860x; 1.0041x over previous
#include <cuda_runtime.h>
#include <cuda_fp16.h>
#include <math.h>
#include <stdint.h>

#define D_DIM 1024
#define H_DIM 2048
#define E_NUM 8
#define CAP   8192
#define N_TOK 8192
#define BM 128
#define BN 256
#define BK 64                            // halves per slab = 128 B rows

#define A_BYTES 16384                    // 128 rows x 128B
#define B_BYTES 32768                    // 256 rows x 128B
#define STAGE_BYTES (A_BYTES + B_BYTES)  // 49152
#define NSTAGE 4
#define SMEM_TOTAL (1024 + NSTAGE * STAGE_BYTES)  // 197632

// ---------------- device scratch ----------------
__device__ int    g_cnt[E_NUM];
__device__ int    g_off[E_NUM];
__device__ int    g_tok[E_NUM * CAP];
__device__ float  g_gate[E_NUM * CAP];
__device__ int    g_inv[N_TOK * 2];
__device__ float  g_imp[E_NUM];
__device__ float  g_ent;
__device__ __half g_xh[(size_t)N_TOK * D_DIM];            // x as half, k-permuted
__device__ __half g_hh[(size_t)N_TOK * 2 * H_DIM];        // h as half, k-permuted
__device__ __half g_yh[(size_t)N_TOK * 2 * D_DIM];        // gate*y as half
__device__ __half g_w1h[(size_t)E_NUM * H_DIM * D_DIM];   // [e][n=H][k'=D]
__device__ __half g_w2h[(size_t)E_NUM * D_DIM * H_DIM];   // [e][n=D][k'=H]

// k-group permutation: storage slot s holds source k = KORD[s]
__device__ __constant__ int KORD[16] = {0,1,8,9,2,3,10,11,4,5,12,13,6,7,14,15};
__device__ __forceinline__ int kslot(int r) {      // r = k & 15, even
    return (((r >> 1) & 3) << 2) + ((r >> 3) << 1);
}

// ---------------- helpers ----------------
__device__ __forceinline__ uint32_t smem_u32(const void* p) {
    uint32_t a;
    asm("{ .reg .u64 t; cvta.to.shared.u64 t, %1; cvt.u32.u64 %0, t; }" : "=r"(a) : "l"(p));
    return a;
}
#define CP16(dst, src) \
    asm volatile("cp.async.cg.shared.global [%0], [%1], 16;" :: "r"(dst), "l"(src))
#define CP_COMMIT()  asm volatile("cp.async.commit_group;" ::: "memory")
#define CP_WAIT(n)   asm volatile("cp.async.wait_group %0;" :: "n"(n) : "memory")

__device__ __forceinline__ void mma_f16(float* c, unsigned a0, unsigned a1,
                                        unsigned a2, unsigned a3,
                                        unsigned b0, unsigned b1) {
    asm volatile(
        "mma.sync.aligned.m16n8k16.row.col.f32.f16.f16.f32 "
        "{%0,%1,%2,%3}, {%4,%5,%6,%7}, {%8,%9}, {%0,%1,%2,%3};\n"
        : "+f"(c[0]), "+f"(c[1]), "+f"(c[2]), "+f"(c[3])
        : "r"(a0), "r"(a1), "r"(a2), "r"(a3), "r"(b0), "r"(b1));
}
__device__ __forceinline__ float gelu_exact(float v) {
    return 0.5f * v * (1.0f + erff(v * 0.70710678118654752440f));
}

// ---------------- small kernels ----------------
__global__ void reset_k() {
    int t = threadIdx.x;
    if (t < E_NUM) { g_cnt[t] = 0; g_imp[t] = 0.0f; }
    if (t == 0)    g_ent = 0.0f;
}

// router + x->half conversion fused (warp per token, gW staged in smem)
__global__ void router_k(const float* __restrict__ x,
                         const float* __restrict__ gW,
                         const float* __restrict__ gb) {
    __shared__ float4 sgW[2048];        // 32 KB, 16B-swizzled
    int tid = threadIdx.x;
    for (int s = tid; s < 2048; s += 256)
        sgW[s ^ ((s >> 3) & 7)] = reinterpret_cast<const float4*>(gW)[s];
    __syncthreads();

    int token = (blockIdx.x * blockDim.x + tid) >> 5;
    int lane  = tid & 31;
    if (token >= N_TOK) return;
    const float* xr = x + (size_t)token * D_DIM;
    __half* xh = g_xh + (size_t)token * D_DIM;

    float acc[8] = {0.f,0.f,0.f,0.f,0.f,0.f,0.f,0.f};
#pragma unroll
    for (int i = 0; i < 8; i++) {
        int d = lane * 4 + 128 * i;
        float4 xv = *reinterpret_cast<const float4*>(xr + d);
        int base = d & ~15, r = d & 15;
        *reinterpret_cast<__half2*>(xh + base + kslot(r)) =
            __floats2half2_rn(xv.x, xv.y);
        *reinterpret_cast<__half2*>(xh + base + kslot(r + 2)) =
            __floats2half2_rn(xv.z, xv.w);
        float xs[4] = {xv.x, xv.y, xv.z, xv.w};
#pragma unroll
        for (int q = 0; q < 4; q++) {
            int s0 = (d + q) * 2;
            float4 wa = sgW[s0 ^ ((s0 >> 3) & 7)];
            int s1 = s0 + 1;
            float4 wb = sgW[s1 ^ ((s1 >> 3) & 7)];
            acc[0] += xs[q] * wa.x; acc[1] += xs[q] * wa.y;
            acc[2] += xs[q] * wa.z; acc[3] += xs[q] * wa.w;
            acc[4] += xs[q] * wb.x; acc[5] += xs[q] * wb.y;
            acc[6] += xs[q] * wb.z; acc[7] += xs[q] * wb.w;
        }
    }
#pragma unroll
    for (int e = 0; e < 8; e++)
#pragma unroll
        for (int o = 16; o; o >>= 1) acc[e] += __shfl_xor_sync(0xffffffffu, acc[e], o);
    if (lane) return;

    float lg[8];
#pragma unroll
    for (int e = 0; e < 8; e++) lg[e] = acc[e] + gb[e];
    float mx = lg[0];
#pragma unroll
    for (int e = 1; e < 8; e++) mx = fmaxf(mx, lg[e]);
    float p[8], Z = 0.f;
#pragma unroll
    for (int e = 0; e < 8; e++) { p[e] = expf(lg[e] - mx); Z += p[e]; }
    float ent = 0.f;
#pragma unroll
    for (int e = 0; e < 8; e++) {
        p[e] /= Z;
        ent -= p[e] * logf(p[e] + 1e-8f);
        atomicAdd(&g_imp[e], p[e]);
    }
    atomicAdd(&g_ent, ent);

    int e0 = 0;
#pragma unroll
    for (int e = 1; e < 8; e++) if (lg[e] > lg[e0]) e0 = e;
    int e1 = -1;
#pragma unroll
    for (int e = 0; e < 8; e++) if (e != e0 && (e1 < 0 || lg[e] > lg[e1])) e1 = e;

    float dlt = expf(lg[e1] - lg[e0]);
    float g0 = 1.0f / (1.0f + dlt);
    float g1 = dlt / (1.0f + dlt);

    int s0 = atomicAdd(&g_cnt[e0], 1);
    g_tok[e0 * CAP + s0] = token; g_gate[e0 * CAP + s0] = g0;
    int s1 = atomicAdd(&g_cnt[e1], 1);
    g_tok[e1 * CAP + s1] = token; g_gate[e1 * CAP + s1] = g1;
    g_inv[token * 2 + 0] = e0 * CAP + s0;
    g_inv[token * 2 + 1] = e1 * CAP + s1;
}

__global__ void tail_k(float* __restrict__ out_tail) {
    if (threadIdx.x != 0 || blockIdx.x != 0) return;
    int off = 0;
    float loadv[8], impv[8];
    for (int e = 0; e < 8; e++) { g_off[e] = off; off += g_cnt[e]; }
    for (int e = 0; e < 8; e++) {
        loadv[e] = (float)g_cnt[e] / (float)N_TOK;
        impv[e]  = g_imp[e] / (float)N_TOK;
    }
    float bal = 0.f, util = 0.f;
    for (int e = 0; e < 8; e++) bal += impv[e] * loadv[e];
    bal *= (float)E_NUM;
    for (int e = 0; e < 8; e++) util -= loadv[e] * logf(loadv[e] + 1e-8f);
    out_tail[0] = bal;
    out_tail[1] = g_ent / (float)N_TOK;
    out_tail[2] = util;
    for (int e = 0; e < 8; e++) out_tail[3 + e]  = loadv[e];
    for (int e = 0; e < 8; e++) out_tail[11 + e] = impv[e];
}

// W[e][k][n] fp32 -> WT[e][n][k'] half. 64x64 tiles.
// Column XOR swizzle keyed on row>>4 -> conflict-free readout AND
// coalesced 128B global stores (4 lanes per n-row).
__global__ void wtrans_k(const float* __restrict__ W, __half* __restrict__ WT,
                         int K, int N) {
    __shared__ float t[64][68];
    int e = blockIdx.z, n0 = blockIdx.x * 64, k0 = blockIdx.y * 64;
    const float* Ws = W + (size_t)e * K * N + (size_t)k0 * N + n0;
    __half* Wd = WT + (size_t)e * N * K;
#pragma unroll
    for (int i = 0; i < 4; i++) {
        int idx = threadIdx.x + 256 * i;     // 0..1023
        int kr = idx >> 4, c4 = idx & 15;
        float4 v = *reinterpret_cast<const float4*>(Ws + (size_t)kr * N + c4 * 4);
        int cs = (c4 * 4) ^ (((kr >> 4) & 3) << 3);   // 8-multiple XOR: float4-safe
        *reinterpret_cast<float4*>(&t[kr][cs]) = v;
    }
    __syncthreads();
    // lane group: 4 kg values x 8 n values -> all 32 banks distinct
    int n = threadIdx.x >> 2, kg = (threadIdx.x & 3) * 16;
    __half hh[16];
#pragma unroll
    for (int s = 0; s < 16; s++) {
        int row = kg + KORD[s];
        hh[s] = __float2half(t[row][n ^ (((row >> 4) & 3) << 3)]);
    }
    __half* drow = Wd + (size_t)(n0 + n) * K + k0 + kg;
    *reinterpret_cast<uint4*>(drow)     = *reinterpret_cast<uint4*>(hh);
    *reinterpret_cast<uint4*>(drow + 8) = *reinterpret_cast<uint4*>(hh + 8);
}

// ---------------- fp16 pipelined grouped GEMM (128x256, warp 64x64, BK=64) ----------------
// MODE 0: A = gather(g_xh) [K=1024], B=g_w1h, bias+gelu -> g_hh (half, permuted)
// MODE 1: A = g_hh [K=2048], B=g_w2h, gate*(bias+c) -> g_yh (half)
template <int MODE>
__global__ void __launch_bounds__(256, 1)
gemm_h(const float* __restrict__ bias) {
    constexpr int Kdim  = (MODE == 0) ? D_DIM : H_DIM;
    constexpr int Ncols = (MODE == 0) ? H_DIM : D_DIM;
    constexpr int NS    = Kdim / BK;

    extern __shared__ char smem[];
    const int e = blockIdx.z;
    const int cnt = g_cnt[e];
    const int m_base = blockIdx.y * BM;
    if (m_base >= cnt) return;
    const int n_base = blockIdx.x * BN;
    const int hoff = g_off[e];

    const int tid = threadIdx.x, wid = tid >> 5, lane = tid & 31;
    const int g = lane >> 2, tig = lane & 3;
    const int wm = (wid & 1) * 64;
    const int wn = (wid >> 1) * 64;
    const uint32_t sb = smem_u32(smem);
    float* sBias = (float*)smem;

    sBias[tid] = bias[(size_t)e * Ncols + n_base + tid];

    // ---- cp.async assignments ----
    const int cch = tid & 7;          // 16B chunk (8 halves) within 128B row
    const int r0  = tid >> 3;         // base row 0..31
    const __half* Ab = (MODE == 0) ? (const __half*)g_xh : (const __half*)g_hh;
    const __half* Wb = (MODE == 0) ? (const __half*)g_w1h : (const __half*)g_w2h;

    const __half* aSrc[4];
#pragma unroll
    for (int i = 0; i < 4; i++) {
        int am = m_base + r0 + 32 * i;
        if (am >= cnt) am = cnt - 1;
        size_t row = (MODE == 0) ? (size_t)g_tok[e * CAP + am] : (size_t)(hoff + am);
        aSrc[i] = Ab + row * Kdim + cch * 8;
    }
    const __half* bSrc = Wb + ((size_t)e * Ncols + n_base + r0) * Kdim + cch * 8;

    const uint32_t swz = (uint32_t)((cch ^ (r0 & 7)) << 4);
    const uint32_t aDst = sb + 1024 + r0 * 128 + swz;
    const uint32_t bDst = sb + 1024 + A_BYTES + r0 * 128 + swz;

    float c[4][8][4];
#pragma unroll
    for (int i = 0; i < 4; i++)
#pragma unroll
        for (int j = 0; j < 8; j++)
#pragma unroll
            for (int r = 0; r < 4; r++) c[i][j][r] = 0.f;

    auto issue = [&](int s) {
        if (s < NS) {
            const int kb = s * BK;
            const uint32_t so = (uint32_t)((s & (NSTAGE - 1)) * STAGE_BYTES);
#pragma unroll
            for (int i = 0; i < 4; i++)
                CP16(aDst + so + i * 4096, aSrc[i] + kb);
#pragma unroll
            for (int i = 0; i < 8; i++)
                CP16(bDst + so + i * 4096, bSrc + (size_t)(32 * i) * Kdim + kb);
        }
        CP_COMMIT();
    };

    issue(0); issue(1); issue(2);

    const int aRow = (wm + g) * 128;
    const int bRow = A_BYTES + (wn + g) * 128;

    for (int s = 0; s < NS; s++) {
        CP_WAIT(2);
        __syncthreads();
        issue(s + 3);

        const char* stg = smem + 1024 + (s & (NSTAGE - 1)) * STAGE_BYTES;
#pragma unroll
        for (int kx = 0; kx < 4; kx++) {
            const int off = (((2 * kx + (tig >> 1)) ^ g) << 4) + 8 * (tig & 1);
            uint2 ua0[4], ua1[4], ub[8];
#pragma unroll
            for (int i = 0; i < 4; i++) {
                ua0[i] = *(const uint2*)(stg + aRow + i * 2048 + off);
                ua1[i] = *(const uint2*)(stg + aRow + i * 2048 + 1024 + off);
            }
#pragma unroll
            for (int j = 0; j < 8; j++)
                ub[j] = *(const uint2*)(stg + bRow + j * 1024 + off);
#pragma unroll
            for (int i = 0; i < 4; i++)
#pragma unroll
                for (int j = 0; j < 8; j++)
                    mma_f16(c[i][j], ua0[i].x, ua1[i].x, ua0[i].y, ua1[i].y,
                            ub[j].x, ub[j].y);
        }
    }

    // ---- epilogue ----
#pragma unroll
    for (int i = 0; i < 4; i++) {
#pragma unroll
        for (int half = 0; half < 2; half++) {
            int mrow = m_base + wm + 16 * i + g + half * 8;
            if (mrow >= cnt) continue;
            if (MODE == 0) {
                __half* hp = g_hh + (size_t)(hoff + mrow) * H_DIM + n_base;
#pragma unroll
                for (int j = 0; j < 8; j++) {
                    int col = wn + j * 8 + tig * 2;
                    float v0 = c[i][j][half * 2 + 0] + sBias[col];
                    float v1 = c[i][j][half * 2 + 1] + sBias[col + 1];
                    int col2 = (col & ~15) + kslot(col & 15);   // permuted store
                    *reinterpret_cast<__half2*>(hp + col2) =
                        __floats2half2_rn(gelu_exact(v0), gelu_exact(v1));
                }
            } else {
                float gate = g_gate[e * CAP + mrow];
                __half* yp = g_yh + (size_t)(hoff + mrow) * D_DIM + n_base;
#pragma unroll
                for (int j = 0; j < 8; j++) {
                    int col = wn + j * 8 + tig * 2;
                    float v0 = gate * (c[i][j][half * 2 + 0] + sBias[col]);
                    float v1 = gate * (c[i][j][half * 2 + 1] + sBias[col + 1]);
                    *reinterpret_cast<__half2*>(yp + col) = __floats2half2_rn(v0, v1);
                }
            }
        }
    }
}

// ---------------- LayerNorm (y pre-gated, fp16) ----------------
__global__ void ln_k(const float* __restrict__ x,
                     const float* __restrict__ gamma,
                     const float* __restrict__ beta,
                     float* __restrict__ out) {
    int t = blockIdx.x;
    int tid = threadIdx.x;
    int lane = tid & 31, wid = tid >> 5;

    int i0 = g_inv[t * 2 + 0], i1 = g_inv[t * 2 + 1];
    size_t r0 = (size_t)(g_off[i0 >> 13] + (i0 & (CAP - 1)));
    size_t r1 = (size_t)(g_off[i1 >> 13] + (i1 & (CAP - 1)));
    const __half* y0 = g_yh + r0 * D_DIM;
    const __half* y1 = g_yh + r1 * D_DIM;
    const float* xr = x + (size_t)t * D_DIM;

    int c = tid * 4;
    float4 xv = *reinterpret_cast<const float4*>(xr + c);
    __half2 a01 = *reinterpret_cast<const __half2*>(y0 + c);
    __half2 a23 = *reinterpret_cast<const __half2*>(y0 + c + 2);
    __half2 b01 = *reinterpret_cast<const __half2*>(y1 + c);
    __half2 b23 = *reinterpret_cast<const __half2*>(y1 + c + 2);
    float2 fa01 = __half22float2(a01), fa23 = __half22float2(a23);
    float2 fb01 = __half22float2(b01), fb23 = __half22float2(b23);
    float z0 = xv.x + fa01.x + fb01.x;
    float z1 = xv.y + fa01.y + fb01.y;
    float z2 = xv.z + fa23.x + fb23.x;
    float z3 = xv.w + fa23.y + fb23.y;

    float s  = z0 + z1 + z2 + z3;
    float sq = z0 * z0 + z1 * z1 + z2 * z2 + z3 * z3;
#pragma unroll
    for (int o = 16; o; o >>= 1) {
        s  += __shfl_xor_sync(0xffffffffu, s, o);
        sq += __shfl_xor_sync(0xffffffffu, sq, o);
    }
    __shared__ float ws[8], wq[8];
    if (lane == 0) { ws[wid] = s; wq[wid] = sq; }
    __syncthreads();
    if (wid == 0) {
        float s2 = (lane < 8) ? ws[lane] : 0.f;
        float q2 = (lane < 8) ? wq[lane] : 0.f;
#pragma unroll
        for (int o = 4; o; o >>= 1) {
            s2 += __shfl_xor_sync(0xffffffffu, s2, o);
            q2 += __shfl_xor_sync(0xffffffffu, q2, o);
        }
        if (lane == 0) { ws[0] = s2; wq[0] = q2; }
    }
    __syncthreads();
    float mu  = ws[0] * (1.0f / D_DIM);
    float var = wq[0] * (1.0f / D_DIM) - mu * mu;
    float inv = rsqrtf(var + 1e-5f);

    float4 gm = *reinterpret_cast<const float4*>(gamma + c);
    float4 bt = *reinterpret_cast<const float4*>(beta + c);
    float4 o;
    o.x = (z0 - mu) * inv * gm.x + bt.x;
    o.y = (z1 - mu) * inv * gm.y + bt.y;
    o.z = (z2 - mu) * inv * gm.z + bt.z;
    o.w = (z3 - mu) * inv * gm.w + bt.w;
    *reinterpret_cast<float4*>(out + (size_t)t * D_DIM + c) = o;
}

// ---------------- launch ----------------
extern "C" void kernel_launch(void* const* d_in, const int* in_sizes, int n_in,
                              void* d_out, int out_size) {
    (void)in_sizes; (void)n_in; (void)out_size;
    const float* x     = (const float*)d_in[0];
    const float* gW    = (const float*)d_in[1];
    const float* gb    = (const float*)d_in[2];
    const float* W1    = (const float*)d_in[3];
    const float* b1    = (const float*)d_in[4];
    const float* W2    = (const float*)d_in[5];
    const float* b2    = (const float*)d_in[6];
    const float* gamma = (const float*)d_in[7];
    const float* beta  = (const float*)d_in[8];
    float* out = (float*)d_out;

    cudaFuncSetAttribute((const void*)gemm_h<0>,
                         cudaFuncAttributeMaxDynamicSharedMemorySize, SMEM_TOTAL);
    cudaFuncSetAttribute((const void*)gemm_h<1>,
                         cudaFuncAttributeMaxDynamicSharedMemorySize, SMEM_TOTAL);

    __half* w1h; cudaGetSymbolAddress((void**)&w1h, g_w1h);
    __half* w2h; cudaGetSymbolAddress((void**)&w2h, g_w2h);

    reset_k<<<1, 32>>>();
    router_k<<<N_TOK / 8, 256>>>(x, gW, gb);
    tail_k<<<1, 1>>>(out + (size_t)N_TOK * D_DIM);
    wtrans_k<<<dim3(H_DIM / 64, D_DIM / 64, E_NUM), 256>>>(W1, w1h, D_DIM, H_DIM);
    wtrans_k<<<dim3(D_DIM / 64, H_DIM / 64, E_NUM), 256>>>(W2, w2h, H_DIM, D_DIM);
    gemm_h<0><<<dim3(H_DIM / BN, CAP / BM, E_NUM), 256, SMEM_TOTAL>>>(b1);
    gemm_h<1><<<dim3(D_DIM / BN, CAP / BM, E_NUM), 256, SMEM_TOTAL>>>(b2);
    ln_k<<<N_TOK, 256>>>(x, gamma, beta, out);
}

// round 11
// speedup vs baseline: 1.0888x; 1.0026x over previous
#include <cuda_runtime.h>
#include <cuda_fp16.h>
#include <math.h>
#include <stdint.h>

#define D_DIM 1024
#define H_DIM 2048
#define E_NUM 8
#define CAP   8192
#define N_TOK 8192
#define BM 128
#define BN 256
#define BK 64                            // halves per slab = 128 B rows

#define A_BYTES 16384                    // 128 rows x 128B
#define B_BYTES 32768                    // 256 rows x 128B
#define STAGE_BYTES (A_BYTES + B_BYTES)  // 49152
#define NSTAGE 4
#define SMEM_TOTAL (1024 + NSTAGE * STAGE_BYTES)  // 197632

// ---------------- device scratch ----------------
__device__ int    g_cnt[E_NUM];
__device__ int    g_off[E_NUM];
__device__ int    g_tok[E_NUM * CAP];
__device__ float  g_gate[E_NUM * CAP];
__device__ int    g_inv[N_TOK * 2];
__device__ float  g_imp[E_NUM];
__device__ float  g_ent;
__device__ __half g_xh[(size_t)N_TOK * D_DIM];            // x as half, k-permuted
__device__ __half g_hh[(size_t)N_TOK * 2 * H_DIM];        // h as half, k-permuted
__device__ __half g_yh[(size_t)N_TOK * 2 * D_DIM];        // gate*y as half
__device__ __half g_w1h[(size_t)E_NUM * H_DIM * D_DIM];   // [e][n=H][k'=D]
__device__ __half g_w2h[(size_t)E_NUM * D_DIM * H_DIM];   // [e][n=D][k'=H]

// k-group permutation: storage slot s holds source k = KORD[s]
__device__ __constant__ int KORD[16] = {0,1,8,9,2,3,10,11,4,5,12,13,6,7,14,15};
__device__ __forceinline__ int kslot(int r) {      // r = k & 15, even
    return (((r >> 1) & 3) << 2) + ((r >> 3) << 1);
}

// ---------------- helpers ----------------
__device__ __forceinline__ uint32_t smem_u32(const void* p) {
    uint32_t a;
    asm("{ .reg .u64 t; cvta.to.shared.u64 t, %1; cvt.u32.u64 %0, t; }" : "=r"(a) : "l"(p));
    return a;
}
#define CP16(dst, src) \
    asm volatile("cp.async.cg.shared.global [%0], [%1], 16;" :: "r"(dst), "l"(src))
#define CP_COMMIT()  asm volatile("cp.async.commit_group;" ::: "memory")
#define CP_WAIT(n)   asm volatile("cp.async.wait_group %0;" :: "n"(n) : "memory")

__device__ __forceinline__ void mma_f16(float* c, unsigned a0, unsigned a1,
                                        unsigned a2, unsigned a3,
                                        unsigned b0, unsigned b1) {
    asm volatile(
        "mma.sync.aligned.m16n8k16.row.col.f32.f16.f16.f32 "
        "{%0,%1,%2,%3}, {%4,%5,%6,%7}, {%8,%9}, {%0,%1,%2,%3};\n"
        : "+f"(c[0]), "+f"(c[1]), "+f"(c[2]), "+f"(c[3])
        : "r"(a0), "r"(a1), "r"(a2), "r"(a3), "r"(b0), "r"(b1));
}
__device__ __forceinline__ float gelu_exact(float v) {
    return 0.5f * v * (1.0f + erff(v * 0.70710678118654752440f));
}

// ---------------- shared bodies ----------------
// W[e][k][n] fp32 -> WT[e][n][k'] half, one 64x64 tile.
// Column XOR swizzle keyed on row>>4: conflict-free smem reads AND
// coalesced 128B global stores.
__device__ __forceinline__ void wtrans_body(const float* __restrict__ W,
                                            __half* __restrict__ WT,
                                            int K, int N, int nbi, int kbi, int e,
                                            float (*t)[68]) {
    int n0 = nbi * 64, k0 = kbi * 64;
    const float* Ws = W + (size_t)e * K * N + (size_t)k0 * N + n0;
    __half* Wd = WT + (size_t)e * N * K;
#pragma unroll
    for (int i = 0; i < 4; i++) {
        int idx = threadIdx.x + 256 * i;     // 0..1023
        int kr = idx >> 4, c4 = idx & 15;
        float4 v = *reinterpret_cast<const float4*>(Ws + (size_t)kr * N + c4 * 4);
        int cs = (c4 * 4) ^ (((kr >> 4) & 3) << 3);   // 8-multiple XOR: float4-safe
        *reinterpret_cast<float4*>(&t[kr][cs]) = v;
    }
    __syncthreads();
    int n = threadIdx.x >> 2, kg = (threadIdx.x & 3) * 16;
    __half hh[16];
#pragma unroll
    for (int s = 0; s < 16; s++) {
        int row = kg + KORD[s];
        hh[s] = __float2half(t[row][n ^ (((row >> 4) & 3) << 3)]);
    }
    __half* drow = Wd + (size_t)(n0 + n) * K + k0 + kg;
    *reinterpret_cast<uint4*>(drow)     = *reinterpret_cast<uint4*>(hh);
    *reinterpret_cast<uint4*>(drow + 8) = *reinterpret_cast<uint4*>(hh + 8);
}

// ---------------- small kernels ----------------
__global__ void reset_k() {
    int t = threadIdx.x;
    if (t < E_NUM) { g_cnt[t] = 0; g_imp[t] = 0.0f; }
    if (t == 0)    g_ent = 0.0f;
}

// prelude: blocks [0,1024) = router (+x->half), blocks [1024,5120) = W1 transpose
__global__ void prelude_k(const float* __restrict__ x,
                          const float* __restrict__ gW,
                          const float* __restrict__ gb,
                          const float* __restrict__ W1) {
    __shared__ __align__(16) char smbuf[32768];

    if (blockIdx.x >= 1024) {
        int lin = blockIdx.x - 1024;         // W1: N=H_DIM (32 tiles), K=D_DIM (16 tiles)
        wtrans_body(W1, g_w1h, D_DIM, H_DIM,
                    lin & 31, (lin >> 5) & 15, lin >> 9,
                    reinterpret_cast<float(*)[68]>(smbuf));
        return;
    }

    float4* sgW = reinterpret_cast<float4*>(smbuf);   // 32 KB, 16B-swizzled
    int tid = threadIdx.x;
    for (int s = tid; s < 2048; s += 256)
        sgW[s ^ ((s >> 3) & 7)] = reinterpret_cast<const float4*>(gW)[s];
    __syncthreads();

    int token = (blockIdx.x * blockDim.x + tid) >> 5;
    int lane  = tid & 31;
    const float* xr = x + (size_t)token * D_DIM;
    __half* xh = g_xh + (size_t)token * D_DIM;

    float acc[8] = {0.f,0.f,0.f,0.f,0.f,0.f,0.f,0.f};
#pragma unroll
    for (int i = 0; i < 8; i++) {
        int d = lane * 4 + 128 * i;
        float4 xv = *reinterpret_cast<const float4*>(xr + d);
        int base = d & ~15, r = d & 15;
        *reinterpret_cast<__half2*>(xh + base + kslot(r)) =
            __floats2half2_rn(xv.x, xv.y);
        *reinterpret_cast<__half2*>(xh + base + kslot(r + 2)) =
            __floats2half2_rn(xv.z, xv.w);
        float xs[4] = {xv.x, xv.y, xv.z, xv.w};
#pragma unroll
        for (int q = 0; q < 4; q++) {
            int s0 = (d + q) * 2;
            float4 wa = sgW[s0 ^ ((s0 >> 3) & 7)];
            int s1 = s0 + 1;
            float4 wb = sgW[s1 ^ ((s1 >> 3) & 7)];
            acc[0] += xs[q] * wa.x; acc[1] += xs[q] * wa.y;
            acc[2] += xs[q] * wa.z; acc[3] += xs[q] * wa.w;
            acc[4] += xs[q] * wb.x; acc[5] += xs[q] * wb.y;
            acc[6] += xs[q] * wb.z; acc[7] += xs[q] * wb.w;
        }
    }
#pragma unroll
    for (int e = 0; e < 8; e++)
#pragma unroll
        for (int o = 16; o; o >>= 1) acc[e] += __shfl_xor_sync(0xffffffffu, acc[e], o);
    if (lane) return;

    float lg[8];
#pragma unroll
    for (int e = 0; e < 8; e++) lg[e] = acc[e] + gb[e];
    float mx = lg[0];
#pragma unroll
    for (int e = 1; e < 8; e++) mx = fmaxf(mx, lg[e]);
    float p[8], Z = 0.f;
#pragma unroll
    for (int e = 0; e < 8; e++) { p[e] = expf(lg[e] - mx); Z += p[e]; }
    float ent = 0.f;
#pragma unroll
    for (int e = 0; e < 8; e++) {
        p[e] /= Z;
        ent -= p[e] * logf(p[e] + 1e-8f);
        atomicAdd(&g_imp[e], p[e]);
    }
    atomicAdd(&g_ent, ent);

    int e0 = 0;
#pragma unroll
    for (int e = 1; e < 8; e++) if (lg[e] > lg[e0]) e0 = e;
    int e1 = -1;
#pragma unroll
    for (int e = 0; e < 8; e++) if (e != e0 && (e1 < 0 || lg[e] > lg[e1])) e1 = e;

    float dlt = expf(lg[e1] - lg[e0]);
    float g0 = 1.0f / (1.0f + dlt);
    float g1 = dlt / (1.0f + dlt);

    int s0 = atomicAdd(&g_cnt[e0], 1);
    g_tok[e0 * CAP + s0] = token; g_gate[e0 * CAP + s0] = g0;
    int s1 = atomicAdd(&g_cnt[e1], 1);
    g_tok[e1 * CAP + s1] = token; g_gate[e1 * CAP + s1] = g1;
    g_inv[token * 2 + 0] = e0 * CAP + s0;
    g_inv[token * 2 + 1] = e1 * CAP + s1;
}

__global__ void tail_k(float* __restrict__ out_tail) {
    if (threadIdx.x != 0 || blockIdx.x != 0) return;
    int off = 0;
    float loadv[8], impv[8];
    for (int e = 0; e < 8; e++) { g_off[e] = off; off += g_cnt[e]; }
    for (int e = 0; e < 8; e++) {
        loadv[e] = (float)g_cnt[e] / (float)N_TOK;
        impv[e]  = g_imp[e] / (float)N_TOK;
    }
    float bal = 0.f, util = 0.f;
    for (int e = 0; e < 8; e++) bal += impv[e] * loadv[e];
    bal *= (float)E_NUM;
    for (int e = 0; e < 8; e++) util -= loadv[e] * logf(loadv[e] + 1e-8f);
    out_tail[0] = bal;
    out_tail[1] = g_ent / (float)N_TOK;
    out_tail[2] = util;
    for (int e = 0; e < 8; e++) out_tail[3 + e]  = loadv[e];
    for (int e = 0; e < 8; e++) out_tail[11 + e] = impv[e];
}

// ---------------- fp16 pipelined grouped GEMM (128x256, warp 64x64, BK=64) ----------------
// MODE 0: A = gather(g_xh) [K=1024], B=g_w1h, bias+gelu -> g_hh (half, permuted)
//         blocks with blockIdx.y >= 64 instead transpose W2 -> g_w2h (hidden overlap)
// MODE 1: A = g_hh [K=2048], B=g_w2h, gate*(bias+c) -> g_yh (half)
template <int MODE>
__global__ void __launch_bounds__(256, 1)
gemm_h(const float* __restrict__ bias, const float* __restrict__ W2) {
    constexpr int Kdim  = (MODE == 0) ? D_DIM : H_DIM;
    constexpr int Ncols = (MODE == 0) ? H_DIM : D_DIM;
    constexpr int NS    = Kdim / BK;

    extern __shared__ char smem[];

    if (MODE == 0 && blockIdx.y >= 64) {
        // W2 transpose: N=D_DIM (16 tiles), K=H_DIM (32 tiles)
        int lin = blockIdx.x + 8 * (blockIdx.y - 64) + 512 * blockIdx.z;
        wtrans_body(W2, g_w2h, H_DIM, D_DIM,
                    lin & 15, (lin >> 4) & 31, lin >> 9,
                    reinterpret_cast<float(*)[68]>(smem));
        return;
    }

    const int e = blockIdx.z;
    const int cnt = g_cnt[e];
    const int m_base = blockIdx.y * BM;
    if (m_base >= cnt) return;
    const int n_base = blockIdx.x * BN;
    const int hoff = g_off[e];

    const int tid = threadIdx.x, wid = tid >> 5, lane = tid & 31;
    const int g = lane >> 2, tig = lane & 3;
    const int wm = (wid & 1) * 64;
    const int wn = (wid >> 1) * 64;
    const uint32_t sb = smem_u32(smem);
    float* sBias = (float*)smem;

    sBias[tid] = bias[(size_t)e * Ncols + n_base + tid];

    // ---- cp.async assignments ----
    const int cch = tid & 7;          // 16B chunk (8 halves) within 128B row
    const int r0  = tid >> 3;         // base row 0..31
    const __half* Ab = (MODE == 0) ? (const __half*)g_xh : (const __half*)g_hh;
    const __half* Wb = (MODE == 0) ? (const __half*)g_w1h : (const __half*)g_w2h;

    const __half* aSrc[4];
#pragma unroll
    for (int i = 0; i < 4; i++) {
        int am = m_base + r0 + 32 * i;
        if (am >= cnt) am = cnt - 1;
        size_t row = (MODE == 0) ? (size_t)g_tok[e * CAP + am] : (size_t)(hoff + am);
        aSrc[i] = Ab + row * Kdim + cch * 8;
    }
    const __half* bSrc = Wb + ((size_t)e * Ncols + n_base + r0) * Kdim + cch * 8;

    const uint32_t swz = (uint32_t)((cch ^ (r0 & 7)) << 4);
    const uint32_t aDst = sb + 1024 + r0 * 128 + swz;
    const uint32_t bDst = sb + 1024 + A_BYTES + r0 * 128 + swz;

    float c[4][8][4];
#pragma unroll
    for (int i = 0; i < 4; i++)
#pragma unroll
        for (int j = 0; j < 8; j++)
#pragma unroll
            for (int r = 0; r < 4; r++) c[i][j][r] = 0.f;

    auto issue = [&](int s) {
        if (s < NS) {
            const int kb = s * BK;
            const uint32_t so = (uint32_t)((s & (NSTAGE - 1)) * STAGE_BYTES);
#pragma unroll
            for (int i = 0; i < 4; i++)
                CP16(aDst + so + i * 4096, aSrc[i] + kb);
#pragma unroll
            for (int i = 0; i < 8; i++)
                CP16(bDst + so + i * 4096, bSrc + (size_t)(32 * i) * Kdim + kb);
        }
        CP_COMMIT();
    };

    issue(0); issue(1); issue(2);

    const int aRow = (wm + g) * 128;
    const int bRow = A_BYTES + (wn + g) * 128;

    for (int s = 0; s < NS; s++) {
        CP_WAIT(2);
        __syncthreads();
        issue(s + 3);

        const char* stg = smem + 1024 + (s & (NSTAGE - 1)) * STAGE_BYTES;
#pragma unroll
        for (int kx = 0; kx < 4; kx++) {
            const int off = (((2 * kx + (tig >> 1)) ^ g) << 4) + 8 * (tig & 1);
            uint2 ua0[4], ua1[4], ub[8];
#pragma unroll
            for (int i = 0; i < 4; i++) {
                ua0[i] = *(const uint2*)(stg + aRow + i * 2048 + off);
                ua1[i] = *(const uint2*)(stg + aRow + i * 2048 + 1024 + off);
            }
#pragma unroll
            for (int j = 0; j < 8; j++)
                ub[j] = *(const uint2*)(stg + bRow + j * 1024 + off);
#pragma unroll
            for (int i = 0; i < 4; i++)
#pragma unroll
                for (int j = 0; j < 8; j++)
                    mma_f16(c[i][j], ua0[i].x, ua1[i].x, ua0[i].y, ua1[i].y,
                            ub[j].x, ub[j].y);
        }
    }

    // ---- epilogue ----
#pragma unroll
    for (int i = 0; i < 4; i++) {
#pragma unroll
        for (int half = 0; half < 2; half++) {
            int mrow = m_base + wm + 16 * i + g + half * 8;
            if (mrow >= cnt) continue;
            if (MODE == 0) {
                __half* hp = g_hh + (size_t)(hoff + mrow) * H_DIM + n_base;
#pragma unroll
                for (int j = 0; j < 8; j++) {
                    int col = wn + j * 8 + tig * 2;
                    float v0 = c[i][j][half * 2 + 0] + sBias[col];
                    float v1 = c[i][j][half * 2 + 1] + sBias[col + 1];
                    int col2 = (col & ~15) + kslot(col & 15);   // permuted store
                    *reinterpret_cast<__half2*>(hp + col2) =
                        __floats2half2_rn(gelu_exact(v0), gelu_exact(v1));
                }
            } else {
                float gate = g_gate[e * CAP + mrow];
                __half* yp = g_yh + (size_t)(hoff + mrow) * D_DIM + n_base;
#pragma unroll
                for (int j = 0; j < 8; j++) {
                    int col = wn + j * 8 + tig * 2;
                    float v0 = gate * (c[i][j][half * 2 + 0] + sBias[col]);
                    float v1 = gate * (c[i][j][half * 2 + 1] + sBias[col + 1]);
                    *reinterpret_cast<__half2*>(yp + col) = __floats2half2_rn(v0, v1);
                }
            }
        }
    }
}

// ---------------- LayerNorm (y pre-gated, fp16) ----------------
__global__ void ln_k(const float* __restrict__ x,
                     const float* __restrict__ gamma,
                     const float* __restrict__ beta,
                     float* __restrict__ out) {
    int t = blockIdx.x;
    int tid = threadIdx.x;
    int lane = tid & 31, wid = tid >> 5;

    int i0 = g_inv[t * 2 + 0], i1 = g_inv[t * 2 + 1];
    size_t r0 = (size_t)(g_off[i0 >> 13] + (i0 & (CAP - 1)));
    size_t r1 = (size_t)(g_off[i1 >> 13] + (i1 & (CAP - 1)));
    const __half* y0 = g_yh + r0 * D_DIM;
    const __half* y1 = g_yh + r1 * D_DIM;
    const float* xr = x + (size_t)t * D_DIM;

    int c = tid * 4;
    float4 xv = *reinterpret_cast<const float4*>(xr + c);
    __half2 a01 = *reinterpret_cast<const __half2*>(y0 + c);
    __half2 a23 = *reinterpret_cast<const __half2*>(y0 + c + 2);
    __half2 b01 = *reinterpret_cast<const __half2*>(y1 + c);
    __half2 b23 = *reinterpret_cast<const __half2*>(y1 + c + 2);
    float2 fa01 = __half22float2(a01), fa23 = __half22float2(a23);
    float2 fb01 = __half22float2(b01), fb23 = __half22float2(b23);
    float z0 = xv.x + fa01.x + fb01.x;
    float z1 = xv.y + fa01.y + fb01.y;
    float z2 = xv.z + fa23.x + fb23.x;
    float z3 = xv.w + fa23.y + fb23.y;

    float s  = z0 + z1 + z2 + z3;
    float sq = z0 * z0 + z1 * z1 + z2 * z2 + z3 * z3;
#pragma unroll
    for (int o = 16; o; o >>= 1) {
        s  += __shfl_xor_sync(0xffffffffu, s, o);
        sq += __shfl_xor_sync(0xffffffffu, sq, o);
    }
    __shared__ float ws[8], wq[8];
    if (lane == 0) { ws[wid] = s; wq[wid] = sq; }
    __syncthreads();
    if (wid == 0) {
        float s2 = (lane < 8) ? ws[lane] : 0.f;
        float q2 = (lane < 8) ? wq[lane] : 0.f;
#pragma unroll
        for (int o = 4; o; o >>= 1) {
            s2 += __shfl_xor_sync(0xffffffffu, s2, o);
            q2 += __shfl_xor_sync(0xffffffffu, q2, o);
        }
        if (lane == 0) { ws[0] = s2; wq[0] = q2; }
    }
    __syncthreads();
    float mu  = ws[0] * (1.0f / D_DIM);
    float var = wq[0] * (1.0f / D_DIM) - mu * mu;
    float inv = rsqrtf(var + 1e-5f);

    float4 gm = *reinterpret_cast<const float4*>(gamma + c);
    float4 bt = *reinterpret_cast<const float4*>(beta + c);
    float4 o;
    o.x = (z0 - mu) * inv * gm.x + bt.x;
    o.y = (z1 - mu) * inv * gm.y + bt.y;
    o.z = (z2 - mu) * inv * gm.z + bt.z;
    o.w = (z3 - mu) * inv * gm.w + bt.w;
    *reinterpret_cast<float4*>(out + (size_t)t * D_DIM + c) = o;
}

// ---------------- launch ----------------
extern "C" void kernel_launch(void* const* d_in, const int* in_sizes, int n_in,
                              void* d_out, int out_size) {
    (void)in_sizes; (void)n_in; (void)out_size;
    const float* x     = (const float*)d_in[0];
    const float* gW    = (const float*)d_in[1];
    const float* gb    = (const float*)d_in[2];
    const float* W1    = (const float*)d_in[3];
    const float* b1    = (const float*)d_in[4];
    const float* W2    = (const float*)d_in[5];
    const float* b2    = (const float*)d_in[6];
    const float* gamma = (const float*)d_in[7];
    const float* beta  = (const float*)d_in[8];
    float* out = (float*)d_out;

    cudaFuncSetAttribute((const void*)gemm_h<0>,
                         cudaFuncAttributeMaxDynamicSharedMemorySize, SMEM_TOTAL);
    cudaFuncSetAttribute((const void*)gemm_h<1>,
                         cudaFuncAttributeMaxDynamicSharedMemorySize, SMEM_TOTAL);

    reset_k<<<1, 32>>>();
    prelude_k<<<1024 + 4096, 256>>>(x, gW, gb, W1);      // router + W1 transpose
    tail_k<<<1, 1>>>(out + (size_t)N_TOK * D_DIM);
    // GEMM1 (by<64) + W2 transpose (by>=64, hidden under the GEMM)
    gemm_h<0><<<dim3(H_DIM / BN, 128, E_NUM), 256, SMEM_TOTAL>>>(b1, W2);
    gemm_h<1><<<dim3(D_DIM / BN, CAP / BM, E_NUM), 256, SMEM_TOTAL>>>(b2, nullptr);
    ln_k<<<N_TOK, 256>>>(x, gamma, beta, out);
}